// round 3
// baseline (speedup 1.0000x reference)
#include <cuda_runtime.h>
#include <cuda_bf16.h>
#include <math_constants.h>

// Problem constants
#define NN 100000
#define EE 1000000
#define ET (NN + EE)        // edges incl. self-loops = 1,100,000
#define GG 64
#define HH 64
#define DIN0 128

// ---------------- device scratch (no allocations allowed) ----------------
__device__ float g_h[(size_t)NN * HH];      // h = x @ W (pre-bias)
__device__ float g_out[(size_t)NN * HH];    // aggregated messages
__device__ float g_act[(size_t)NN * HH];    // relu(out + b) -> next layer input
__device__ float g_as[NN];                  // h . a_src per node
__device__ float g_ad[NN];                  // h . a_dst per node
__device__ float g_m[NN];                   // segment max per dst
__device__ float g_den[NN];                 // segment sum per dst
__device__ float g_e[ET];                   // per-edge score -> numerator
__device__ float g_pool[GG * HH];
__device__ int   g_root[GG];

// ---------------- helpers ----------------
__device__ __forceinline__ void atomicMaxF(float* addr, float v) {
    if (v >= 0.f) atomicMax((int*)addr, __float_as_int(v));
    else          atomicMin((unsigned int*)addr, __float_as_uint(v));
}

// ---------------- per-layer init ----------------
__global__ void k_init_layer() {
    int i = blockIdx.x * blockDim.x + threadIdx.x;
    if (i < NN) { g_m[i] = -CUDART_INF_F; g_den[i] = 0.f; }
    const long total = (long)NN * HH;
    const long stride = (long)gridDim.x * blockDim.x;
    for (long j = i; j < total; j += stride) g_out[j] = 0.f;
}

// ---------------- GEMM: C[N,64] = A[N,DIN] @ W[DIN,64] ----------------
// 64x64 tile, BK=16, blockDim (16,16), 4x4 micro-tile per thread.
template <int DIN>
__global__ void k_gemm(const float* __restrict__ A, const float* __restrict__ W) {
    __shared__ float As[64][16];
    __shared__ float Bs[16][64];

    const float* Ap = A ? A : g_act;   // layers 2/3 read g_act
    int tid  = threadIdx.y * 16 + threadIdx.x;
    int row0 = blockIdx.x * 64;

    int lr = tid >> 2, lq = tid & 3;   // A loader: row, float4 slot
    int bk = tid >> 4, bq = tid & 15;  // B loader: k row, float4 slot

    float acc[4][4] = {};

    for (int k0 = 0; k0 < DIN; k0 += 16) {
        int ar = row0 + lr;
        float4 av = make_float4(0.f, 0.f, 0.f, 0.f);
        if (ar < NN) av = *(const float4*)(Ap + (size_t)ar * DIN + k0 + lq * 4);
        *(float4*)(&As[lr][lq * 4]) = av;

        float4 bv = *(const float4*)(W + (size_t)(k0 + bk) * 64 + bq * 4);
        *(float4*)(&Bs[bk][bq * 4]) = bv;
        __syncthreads();

#pragma unroll
        for (int k = 0; k < 16; k++) {
            float a0 = As[threadIdx.y * 4 + 0][k];
            float a1 = As[threadIdx.y * 4 + 1][k];
            float a2 = As[threadIdx.y * 4 + 2][k];
            float a3 = As[threadIdx.y * 4 + 3][k];
            float4 b = *(float4*)(&Bs[k][threadIdx.x * 4]);
            acc[0][0] += a0 * b.x; acc[0][1] += a0 * b.y; acc[0][2] += a0 * b.z; acc[0][3] += a0 * b.w;
            acc[1][0] += a1 * b.x; acc[1][1] += a1 * b.y; acc[1][2] += a1 * b.z; acc[1][3] += a1 * b.w;
            acc[2][0] += a2 * b.x; acc[2][1] += a2 * b.y; acc[2][2] += a2 * b.z; acc[2][3] += a2 * b.w;
            acc[3][0] += a3 * b.x; acc[3][1] += a3 * b.y; acc[3][2] += a3 * b.z; acc[3][3] += a3 * b.w;
        }
        __syncthreads();
    }

#pragma unroll
    for (int i = 0; i < 4; i++) {
        int r = row0 + threadIdx.y * 4 + i;
        if (r < NN) {
            float4 v = make_float4(acc[i][0], acc[i][1], acc[i][2], acc[i][3]);
            *(float4*)(g_h + (size_t)r * 64 + threadIdx.x * 4) = v;
        }
    }
}

// ---------------- alpha: as = h.a_src, ad = h.a_dst (warp per node) ----------------
__global__ void k_alpha(const float* __restrict__ asrc, const float* __restrict__ adst) {
    int gtid = blockIdx.x * blockDim.x + threadIdx.x;
    int node = gtid >> 5;
    int lane = threadIdx.x & 31;
    if (node >= NN) return;
    const float* hr = g_h + (size_t)node * 64;
    float h0 = hr[lane], h1 = hr[lane + 32];
    float s = h0 * asrc[lane] + h1 * asrc[lane + 32];
    float d = h0 * adst[lane] + h1 * adst[lane + 32];
#pragma unroll
    for (int o = 16; o; o >>= 1) {
        s += __shfl_xor_sync(0xFFFFFFFFu, s, o);
        d += __shfl_xor_sync(0xFFFFFFFFu, d, o);
    }
    if (lane == 0) { g_as[node] = s; g_ad[node] = d; }
}

// ---------------- edge pass 1: scores + segment max ----------------
__global__ void k_edge_max(const int* __restrict__ src, const int* __restrict__ dst) {
    int e = blockIdx.x * blockDim.x + threadIdx.x;
    if (e >= ET) return;
    int s, d;
    if (e < EE) { s = src[e]; d = dst[e]; } else { s = d = e - EE; }
    float v = g_as[s] + g_ad[d];
    v = (v >= 0.f) ? v : 0.2f * v;     // leaky_relu(0.2)
    g_e[e] = v;
    atomicMaxF(&g_m[d], v);
}

// ---------------- edge pass 2: exp + segment sum ----------------
__global__ void k_edge_sum(const int* __restrict__ src, const int* __restrict__ dst) {
    int e = blockIdx.x * blockDim.x + threadIdx.x;
    if (e >= ET) return;
    int d = (e < EE) ? dst[e] : (e - EE);
    float num = __expf(g_e[e] - g_m[d]);
    g_e[e] = num;
    atomicAdd(&g_den[d], num);
}

// ---------------- edge pass 3: aggregate coef * h[src] into out[dst] ----------------
// 16 lanes per edge, one float4 vector atomic per lane.
__global__ void k_edge_agg(const int* __restrict__ src, const int* __restrict__ dst) {
    long tid = (long)blockIdx.x * blockDim.x + threadIdx.x;
    long e = tid >> 4;
    int lane = (int)(tid & 15);
    if (e >= ET) return;
    int s, d;
    if (e < EE) { s = src[e]; d = dst[e]; } else { s = d = (int)(e - EE); }
    float coef = g_e[e] / (g_den[d] + 1e-16f);
    float4 hv = ((const float4*)(g_h + (size_t)s * 64))[lane];
    float4 v = make_float4(hv.x * coef, hv.y * coef, hv.z * coef, hv.w * coef);
    atomicAdd(((float4*)(g_out + (size_t)d * 64)) + lane, v);
}

// ---------------- finalize: act = relu(out + b) ----------------
__global__ void k_finalize(const float* __restrict__ b) {
    long i = (long)blockIdx.x * blockDim.x + threadIdx.x;
    if (i >= (long)NN * HH) return;
    int c = (int)(i & 63);
    g_act[i] = fmaxf(g_out[i] + b[c], 0.f);
}

// ---------------- pooling init ----------------
__global__ void k_init_final() {
    int i = blockIdx.x * blockDim.x + threadIdx.x;
    if (i < GG * HH) g_pool[i] = -CUDART_INF_F;
    if (i < GG) g_root[i] = 0x7FFFFFFF;
}

// ---------------- global max pool per graph (batch sorted) ----------------
__global__ void k_pool(const int* __restrict__ batch) {
    int n0 = blockIdx.x * 128;
    int c = threadIdx.x;          // 0..63
    int nend = min(n0 + 128, NN);
    float cur = 0.f; int curg = -1;
    for (int n = n0 + threadIdx.y; n < nend; n += 4) {
        int g = batch[n];
        float v = g_act[(size_t)n * 64 + c];
        if (g != curg) {
            if (curg >= 0) atomicMaxF(&g_pool[curg * 64 + c], cur);
            curg = g; cur = v;
        } else {
            cur = fmaxf(cur, v);
        }
    }
    if (curg >= 0) atomicMaxF(&g_pool[curg * 64 + c], cur);
}

// ---------------- root node per graph (first index; batch sorted) ----------------
__global__ void k_root(const int* __restrict__ batch) {
    int i = blockIdx.x * blockDim.x + threadIdx.x;
    if (i >= NN) return;
    int g = batch[i];
    if (i == 0 || batch[i - 1] != g) atomicMin(&g_root[g], i);
}

// ---------------- head: lin0 / linnews / lin1 / sigmoid ----------------
__global__ void k_head(const float* __restrict__ x,
                       const float* __restrict__ lnW, const float* __restrict__ lnb,
                       const float* __restrict__ l0W, const float* __restrict__ l0b,
                       const float* __restrict__ l1W, const float* __restrict__ l1b,
                       float* __restrict__ out) {
    int g = blockIdx.x;
    int c = threadIdx.x;   // 0..63
    __shared__ float red[2];

    float acc = l0b[c];
#pragma unroll 8
    for (int k = 0; k < 64; k++) acc += g_pool[g * 64 + k] * l0W[k * 64 + c];
    float hp = fmaxf(acc, 0.f);

    const float* xr = x + (size_t)g_root[g] * DIN0;
    float accn = lnb[c];
#pragma unroll 8
    for (int k = 0; k < 128; k++) accn += xr[k] * lnW[k * 64 + c];
    float nw = fmaxf(accn, 0.f);

    float p = hp * l1W[c] + nw * l1W[64 + c];
#pragma unroll
    for (int o = 16; o; o >>= 1) p += __shfl_xor_sync(0xFFFFFFFFu, p, o);
    if ((c & 31) == 0) red[c >> 5] = p;
    __syncthreads();
    if (c == 0) {
        float z = red[0] + red[1] + l1b[0];
        out[g] = 1.f / (1.f + __expf(-z));
    }
}

// ---------------- launch ----------------
extern "C" void kernel_launch(void* const* d_in, const int* in_sizes, int n_in,
                              void* d_out, int out_size) {
    const float* x      = (const float*)d_in[0];
    const int*   adj    = (const int*)d_in[1];
    const int*   batch  = (const int*)d_in[2];
    const float* W1     = (const float*)d_in[3];
    const float* asrc1  = (const float*)d_in[4];
    const float* adst1  = (const float*)d_in[5];
    const float* b1     = (const float*)d_in[6];
    const float* W2     = (const float*)d_in[7];
    const float* asrc2  = (const float*)d_in[8];
    const float* adst2  = (const float*)d_in[9];
    const float* b2     = (const float*)d_in[10];
    const float* W3     = (const float*)d_in[11];
    const float* asrc3  = (const float*)d_in[12];
    const float* adst3  = (const float*)d_in[13];
    const float* b3     = (const float*)d_in[14];
    const float* lnW    = (const float*)d_in[15];
    const float* lnb    = (const float*)d_in[16];
    const float* l0W    = (const float*)d_in[17];
    const float* l0b    = (const float*)d_in[18];
    const float* l1W    = (const float*)d_in[19];
    const float* l1b    = (const float*)d_in[20];
    float* out = (float*)d_out;

    const int* src = adj;
    const int* dst = adj + EE;

    const int GEMM_GRID = (NN + 63) / 64;           // 1563
    const dim3 GEMM_BLK(16, 16);
    const int ALPHA_GRID = (NN * 32 + 255) / 256;   // 12500
    const int INIT_GRID  = (NN + 255) / 256;        // 391
    const int EDGE_GRID  = (ET + 255) / 256;        // 4297
    const long AGG_T     = (long)ET * 16;
    const int AGG_GRID   = (int)((AGG_T + 255) / 256);  // 68750
    const int FIN_GRID   = (NN * HH) / 256;         // 25000

    // ---- layer 1 (DIN=128, input x) ----
    k_gemm<128><<<GEMM_GRID, GEMM_BLK>>>(x, W1);
    k_alpha<<<ALPHA_GRID, 256>>>(asrc1, adst1);
    k_init_layer<<<INIT_GRID, 256>>>();
    k_edge_max<<<EDGE_GRID, 256>>>(src, dst);
    k_edge_sum<<<EDGE_GRID, 256>>>(src, dst);
    k_edge_agg<<<AGG_GRID, 256>>>(src, dst);
    k_finalize<<<FIN_GRID, 256>>>(b1);

    // ---- layer 2 (DIN=64, input g_act via nullptr) ----
    k_gemm<64><<<GEMM_GRID, GEMM_BLK>>>(nullptr, W2);
    k_alpha<<<ALPHA_GRID, 256>>>(asrc2, adst2);
    k_init_layer<<<INIT_GRID, 256>>>();
    k_edge_max<<<EDGE_GRID, 256>>>(src, dst);
    k_edge_sum<<<EDGE_GRID, 256>>>(src, dst);
    k_edge_agg<<<AGG_GRID, 256>>>(src, dst);
    k_finalize<<<FIN_GRID, 256>>>(b2);

    // ---- layer 3 ----
    k_gemm<64><<<GEMM_GRID, GEMM_BLK>>>(nullptr, W3);
    k_alpha<<<ALPHA_GRID, 256>>>(asrc3, adst3);
    k_init_layer<<<INIT_GRID, 256>>>();
    k_edge_max<<<EDGE_GRID, 256>>>(src, dst);
    k_edge_sum<<<EDGE_GRID, 256>>>(src, dst);
    k_edge_agg<<<AGG_GRID, 256>>>(src, dst);
    k_finalize<<<FIN_GRID, 256>>>(b3);

    // ---- head ----
    k_init_final<<<(GG * HH + 255) / 256, 256>>>();
    k_pool<<<(NN + 127) / 128, dim3(64, 4)>>>(batch);
    k_root<<<(NN + 255) / 256, 256>>>(batch);
    k_head<<<GG, 64>>>(x, lnW, lnb, l0W, l0b, l1W, l1b, out);
}

// round 5
// speedup vs baseline: 1.4453x; 1.4453x over previous
#include <cuda_runtime.h>
#include <cuda_bf16.h>
#include <math_constants.h>

// Problem constants
#define NN 100000
#define EE 1000000
#define ET (NN + EE)        // edges incl. self-loops = 1,100,000
#define GG 64
#define HH 64
#define DIN0 128
#define NBLK ((NN + 255) / 256)   // 391

// ---------------- device scratch (no allocations allowed) ----------------
__device__ float g_h[(size_t)NN * HH];      // h = x @ W (pre-bias)
__device__ float g_act[(size_t)NN * HH];    // relu(agg + b) -> next layer input
__device__ float g_as[NN];                  // h . a_src per node
__device__ float g_ad[NN];                  // h . a_dst per node
__device__ float g_pool[GG * HH];
__device__ int   g_root[GG];

// CSR by dst (rebuilt every call; graph static across layers)
__device__ int g_deg[NN];
__device__ int g_tmp[NN];          // block-local exclusive scan
__device__ int g_part[NBLK];       // per-block sums -> scanned
__device__ int g_row[NN + 1];
__device__ int g_cursor[NN];
__device__ int g_csr_src[ET];

// ---------------- helpers ----------------
__device__ __forceinline__ void atomicMaxF(float* addr, float v) {
    if (v >= 0.f) atomicMax((int*)addr, __float_as_int(v));
    else          atomicMin((unsigned int*)addr, __float_as_uint(v));
}

__device__ __forceinline__ unsigned long long pk2(float lo, float hi) {
    unsigned long long r;
    asm("mov.b64 %0, {%1,%2};" : "=l"(r) : "f"(lo), "f"(hi));
    return r;
}
__device__ __forceinline__ void unpk2(unsigned long long v, float& lo, float& hi) {
    asm("mov.b64 {%0,%1}, %2;" : "=f"(lo), "=f"(hi) : "l"(v));
}
__device__ __forceinline__ void fma2(unsigned long long& acc, unsigned long long a,
                                     unsigned long long b) {
    asm("fma.rn.f32x2 %0, %1, %2, %0;" : "+l"(acc) : "l"(a), "l"(b));
}

// ================= CSR build =================
__global__ void k_zero_deg() {
    int i = blockIdx.x * blockDim.x + threadIdx.x;
    if (i < NN) g_deg[i] = 0;
}

__global__ void k_hist(const int* __restrict__ dst) {
    int e = blockIdx.x * blockDim.x + threadIdx.x;
    if (e >= ET) return;
    int d = (e < EE) ? dst[e] : (e - EE);
    atomicAdd(&g_deg[d], 1);
}

__global__ void k_scan_block() {
    __shared__ int sm[256];
    int t = threadIdx.x;
    int i = blockIdx.x * 256 + t;
    int v = (i < NN) ? g_deg[i] : 0;
    sm[t] = v;
    __syncthreads();
#pragma unroll
    for (int off = 1; off < 256; off <<= 1) {
        int u = (t >= off) ? sm[t - off] : 0;
        __syncthreads();
        sm[t] += u;
        __syncthreads();
    }
    if (i < NN) g_tmp[i] = sm[t] - v;       // exclusive within block
    if (t == 255) g_part[blockIdx.x] = sm[255];
}

__global__ void k_scan_part() {
    __shared__ int sm[512];
    int t = threadIdx.x;
    int v = (t < NBLK) ? g_part[t] : 0;
    sm[t] = v;
    __syncthreads();
#pragma unroll
    for (int off = 1; off < 512; off <<= 1) {
        int u = (t >= off) ? sm[t - off] : 0;
        __syncthreads();
        sm[t] += u;
        __syncthreads();
    }
    if (t < NBLK) g_part[t] = sm[t] - v;    // exclusive
}

__global__ void k_scan_add() {
    int i = blockIdx.x * blockDim.x + threadIdx.x;
    if (i < NN) {
        int r = g_tmp[i] + g_part[i >> 8];
        g_row[i] = r;
        g_cursor[i] = r;
    }
    if (i == 0) g_row[NN] = ET;
}

__global__ void k_scatter(const int* __restrict__ src, const int* __restrict__ dst) {
    int e = blockIdx.x * blockDim.x + threadIdx.x;
    if (e >= ET) return;
    int s, d;
    if (e < EE) { s = src[e]; d = dst[e]; } else { s = d = e - EE; }
    int pos = atomicAdd(&g_cursor[d], 1);
    g_csr_src[pos] = s;
}

// ================= GEMM: C[N,64] = A[N,DIN] @ W[DIN,64] =================
// 64x64 tile, BK=16, blockDim (16,16), 4x4 micro-tile, packed f32x2 FMA.
template <int DIN>
__global__ void k_gemm(const float* __restrict__ A, const float* __restrict__ W) {
    __shared__ float2 As2[16][66];   // duplicated pairs {a,a}; row stride even -> 16B alignment
    __shared__ float  Bs[16][64];

    const float* Ap = A ? A : g_act;
    int tx = threadIdx.x, ty = threadIdx.y;
    int tid = ty * 16 + tx;
    int row0 = blockIdx.x * 64;

    int lr = tid >> 2, lq = tid & 3;   // A loader: row, float4 slot
    int bk = tid >> 4, bq = tid & 15;  // B loader: k row, float4 slot

    unsigned long long acc[4][2] = {};   // 4 rows x 4 cols (as 2 f32x2)

    for (int k0 = 0; k0 < DIN; k0 += 16) {
        int ar = row0 + lr;
        float4 av = make_float4(0.f, 0.f, 0.f, 0.f);
        if (ar < NN) av = *(const float4*)(Ap + (size_t)ar * DIN + k0 + lq * 4);
        As2[lq * 4 + 0][lr] = make_float2(av.x, av.x);
        As2[lq * 4 + 1][lr] = make_float2(av.y, av.y);
        As2[lq * 4 + 2][lr] = make_float2(av.z, av.z);
        As2[lq * 4 + 3][lr] = make_float2(av.w, av.w);

        float4 bv = *(const float4*)(W + (size_t)(k0 + bk) * 64 + bq * 4);
        *(float4*)(&Bs[bk][bq * 4]) = bv;
        __syncthreads();

#pragma unroll
        for (int k = 0; k < 16; k++) {
            float4 b = *(float4*)(&Bs[k][tx * 4]);
            unsigned long long b01 = pk2(b.x, b.y);
            unsigned long long b23 = pk2(b.z, b.w);
            // two LDS.128 fetch 4 duplicated a-pairs
            unsigned long long a01[2], a23[2];
            *(float4*)a01 = *(float4*)(&As2[k][ty * 4 + 0]);
            *(float4*)a23 = *(float4*)(&As2[k][ty * 4 + 2]);
            fma2(acc[0][0], a01[0], b01); fma2(acc[0][1], a01[0], b23);
            fma2(acc[1][0], a01[1], b01); fma2(acc[1][1], a01[1], b23);
            fma2(acc[2][0], a23[0], b01); fma2(acc[2][1], a23[0], b23);
            fma2(acc[3][0], a23[1], b01); fma2(acc[3][1], a23[1], b23);
        }
        __syncthreads();
    }

#pragma unroll
    for (int i = 0; i < 4; i++) {
        int r = row0 + ty * 4 + i;
        if (r < NN) {
            float4 v;
            unpk2(acc[i][0], v.x, v.y);
            unpk2(acc[i][1], v.z, v.w);
            *(float4*)(g_h + (size_t)r * 64 + tx * 4) = v;
        }
    }
}

// ================= alpha: as = h.a_src, ad = h.a_dst (warp per node) =================
__global__ void k_alpha(const float* __restrict__ asrc, const float* __restrict__ adst) {
    int gtid = blockIdx.x * blockDim.x + threadIdx.x;
    int node = gtid >> 5;
    int lane = threadIdx.x & 31;
    if (node >= NN) return;
    const float* hr = g_h + (size_t)node * 64;
    float h0 = hr[lane], h1 = hr[lane + 32];
    float s = h0 * asrc[lane] + h1 * asrc[lane + 32];
    float d = h0 * adst[lane] + h1 * adst[lane + 32];
#pragma unroll
    for (int o = 16; o; o >>= 1) {
        s += __shfl_xor_sync(0xFFFFFFFFu, s, o);
        d += __shfl_xor_sync(0xFFFFFFFFu, d, o);
    }
    if (lane == 0) { g_as[node] = s; g_ad[node] = d; }
}

// ================= fused GAT aggregation: warp per dst node =================
// softmax over incoming edges + weighted sum of h[src] + bias + relu, no atomics.
__global__ void k_gat_agg(const float* __restrict__ b) {
    int wg = (blockIdx.x * blockDim.x + threadIdx.x) >> 5;
    int lane = threadIdx.x & 31;
    if (wg >= NN) return;
    int row = g_row[wg], end = g_row[wg + 1];
    float ad = g_ad[wg];

    // pass 1: segment max (lanes parallel over edges)
    float m = -CUDART_INF_F;
    for (int i = row + lane; i < end; i += 32) {
        float v = g_as[g_csr_src[i]] + ad;
        v = fmaxf(v, 0.2f * v);          // leaky_relu(0.2)
        m = fmaxf(m, v);
    }
#pragma unroll
    for (int o = 16; o; o >>= 1) m = fmaxf(m, __shfl_xor_sync(0xFFFFFFFFu, m, o));

    // pass 2: numerators + weighted accumulation (chunks of 32 edges)
    float den = 0.f, acc0 = 0.f, acc1 = 0.f;
    for (int base = row; base < end; base += 32) {
        int i = base + lane;
        int s = 0; float num = 0.f;
        if (i < end) {
            s = g_csr_src[i];
            float v = g_as[s] + ad;
            v = fmaxf(v, 0.2f * v);
            num = __expf(v - m);
        }
        den += num;
        int cnt = min(32, end - base);
        for (int j = 0; j < cnt; j++) {
            float c = __shfl_sync(0xFFFFFFFFu, num, j);
            int  ss = __shfl_sync(0xFFFFFFFFu, s, j);
            const float* hp = g_h + (size_t)ss * 64;
            acc0 += c * hp[lane];
            acc1 += c * hp[lane + 32];
        }
    }
#pragma unroll
    for (int o = 16; o; o >>= 1) den += __shfl_xor_sync(0xFFFFFFFFu, den, o);

    float inv = 1.f / (den + 1e-16f);
    g_act[(size_t)wg * 64 + lane]      = fmaxf(acc0 * inv + b[lane],      0.f);
    g_act[(size_t)wg * 64 + lane + 32] = fmaxf(acc1 * inv + b[lane + 32], 0.f);
}

// ================= pooling / head =================
__global__ void k_init_final() {
    int i = blockIdx.x * blockDim.x + threadIdx.x;
    if (i < GG * HH) g_pool[i] = -CUDART_INF_F;
    if (i < GG) g_root[i] = 0x7FFFFFFF;
}

__global__ void k_pool(const int* __restrict__ batch) {
    int n0 = blockIdx.x * 128;
    int c = threadIdx.x;          // 0..63
    int nend = min(n0 + 128, NN);
    float cur = 0.f; int curg = -1;
    for (int n = n0 + threadIdx.y; n < nend; n += 4) {
        int g = batch[n];
        float v = g_act[(size_t)n * 64 + c];
        if (g != curg) {
            if (curg >= 0) atomicMaxF(&g_pool[curg * 64 + c], cur);
            curg = g; cur = v;
        } else {
            cur = fmaxf(cur, v);
        }
    }
    if (curg >= 0) atomicMaxF(&g_pool[curg * 64 + c], cur);
}

__global__ void k_root(const int* __restrict__ batch) {
    int i = blockIdx.x * blockDim.x + threadIdx.x;
    if (i >= NN) return;
    int g = batch[i];
    if (i == 0 || batch[i - 1] != g) atomicMin(&g_root[g], i);
}

__global__ void k_head(const float* __restrict__ x,
                       const float* __restrict__ lnW, const float* __restrict__ lnb,
                       const float* __restrict__ l0W, const float* __restrict__ l0b,
                       const float* __restrict__ l1W, const float* __restrict__ l1b,
                       float* __restrict__ out) {
    int g = blockIdx.x;
    int c = threadIdx.x;   // 0..63
    __shared__ float red[2];

    float acc = l0b[c];
#pragma unroll 8
    for (int k = 0; k < 64; k++) acc += g_pool[g * 64 + k] * l0W[k * 64 + c];
    float hp = fmaxf(acc, 0.f);

    const float* xr = x + (size_t)g_root[g] * DIN0;
    float accn = lnb[c];
#pragma unroll 8
    for (int k = 0; k < 128; k++) accn += xr[k] * lnW[k * 64 + c];
    float nw = fmaxf(accn, 0.f);

    float p = hp * l1W[c] + nw * l1W[64 + c];
#pragma unroll
    for (int o = 16; o; o >>= 1) p += __shfl_xor_sync(0xFFFFFFFFu, p, o);
    if ((c & 31) == 0) red[c >> 5] = p;
    __syncthreads();
    if (c == 0) {
        float z = red[0] + red[1] + l1b[0];
        out[g] = 1.f / (1.f + __expf(-z));
    }
}

// ================= launch =================
extern "C" void kernel_launch(void* const* d_in, const int* in_sizes, int n_in,
                              void* d_out, int out_size) {
    const float* x      = (const float*)d_in[0];
    const int*   adj    = (const int*)d_in[1];
    const int*   batch  = (const int*)d_in[2];
    const float* W1     = (const float*)d_in[3];
    const float* asrc1  = (const float*)d_in[4];
    const float* adst1  = (const float*)d_in[5];
    const float* b1     = (const float*)d_in[6];
    const float* W2     = (const float*)d_in[7];
    const float* asrc2  = (const float*)d_in[8];
    const float* adst2  = (const float*)d_in[9];
    const float* b2     = (const float*)d_in[10];
    const float* W3     = (const float*)d_in[11];
    const float* asrc3  = (const float*)d_in[12];
    const float* adst3  = (const float*)d_in[13];
    const float* b3     = (const float*)d_in[14];
    const float* lnW    = (const float*)d_in[15];
    const float* lnb    = (const float*)d_in[16];
    const float* l0W    = (const float*)d_in[17];
    const float* l0b    = (const float*)d_in[18];
    const float* l1W    = (const float*)d_in[19];
    const float* l1b    = (const float*)d_in[20];
    float* out = (float*)d_out;

    const int* src = adj;
    const int* dst = adj + EE;

    const int GEMM_GRID  = (NN + 63) / 64;            // 1563
    const dim3 GEMM_BLK(16, 16);
    const int ALPHA_GRID = (NN * 32 + 255) / 256;     // 12500
    const int EDGE_GRID  = (ET + 255) / 256;          // 4297
    const int AGG_GRID   = (NN * 32 + 255) / 256;     // warp per node

    // ---- build dst-CSR once (reused by all 3 layers) ----
    k_zero_deg<<<NBLK, 256>>>();
    k_hist<<<EDGE_GRID, 256>>>(dst);
    k_scan_block<<<NBLK, 256>>>();
    k_scan_part<<<1, 512>>>();
    k_scan_add<<<NBLK, 256>>>();
    k_scatter<<<EDGE_GRID, 256>>>(src, dst);

    // ---- layer 1 (DIN=128, input x) ----
    k_gemm<128><<<GEMM_GRID, GEMM_BLK>>>(x, W1);
    k_alpha<<<ALPHA_GRID, 256>>>(asrc1, adst1);
    k_gat_agg<<<AGG_GRID, 256>>>(b1);

    // ---- layer 2 (DIN=64, input g_act via nullptr) ----
    k_gemm<64><<<GEMM_GRID, GEMM_BLK>>>(nullptr, W2);
    k_alpha<<<ALPHA_GRID, 256>>>(asrc2, adst2);
    k_gat_agg<<<AGG_GRID, 256>>>(b2);

    // ---- layer 3 ----
    k_gemm<64><<<GEMM_GRID, GEMM_BLK>>>(nullptr, W3);
    k_alpha<<<ALPHA_GRID, 256>>>(asrc3, adst3);
    k_gat_agg<<<AGG_GRID, 256>>>(b3);

    // ---- head ----
    k_init_final<<<(GG * HH + 255) / 256, 256>>>();
    k_pool<<<(NN + 127) / 128, dim3(64, 4)>>>(batch);
    k_root<<<(NN + 255) / 256, 256>>>(batch);
    k_head<<<GG, 64>>>(x, lnW, lnb, l0W, l0b, l1W, l1b, out);
}

// round 6
// speedup vs baseline: 1.5591x; 1.0788x over previous
#include <cuda_runtime.h>
#include <cuda_bf16.h>
#include <math_constants.h>

// Problem constants
#define NN 100000
#define EE 1000000
#define ET (NN + EE)        // edges incl. self-loops = 1,100,000
#define GG 64
#define HH 64
#define DIN0 128
#define NBLK ((NN + 255) / 256)   // 391

// ---------------- device scratch (no allocations allowed) ----------------
__device__ float g_h[(size_t)NN * HH];      // h = x @ W (pre-bias)
__device__ float g_act[(size_t)NN * HH];    // relu(agg + b) -> next layer input
__device__ float g_as[NN];                  // h . a_src per node
__device__ float g_ad[NN];                  // h . a_dst per node
__device__ float g_pool[GG * HH];
__device__ int   g_root[GG];

// CSR by dst (rebuilt every call; graph static across layers)
__device__ int g_deg[NN];
__device__ int g_tmp[NN];          // block-local exclusive scan
__device__ int g_part[NBLK];       // per-block sums -> scanned
__device__ int g_row[NN + 1];
__device__ int g_cursor[NN];
__device__ int g_csr_src[ET];

// ---------------- helpers ----------------
__device__ __forceinline__ void atomicMaxF(float* addr, float v) {
    if (v >= 0.f) atomicMax((int*)addr, __float_as_int(v));
    else          atomicMin((unsigned int*)addr, __float_as_uint(v));
}

__device__ __forceinline__ unsigned long long pk2(float lo, float hi) {
    unsigned long long r;
    asm("mov.b64 %0, {%1,%2};" : "=l"(r) : "f"(lo), "f"(hi));
    return r;
}
__device__ __forceinline__ void unpk2(unsigned long long v, float& lo, float& hi) {
    asm("mov.b64 {%0,%1}, %2;" : "=f"(lo), "=f"(hi) : "l"(v));
}
__device__ __forceinline__ void fma2(unsigned long long& acc, unsigned long long a,
                                     unsigned long long b) {
    asm("fma.rn.f32x2 %0, %1, %2, %0;" : "+l"(acc) : "l"(a), "l"(b));
}

// ================= CSR build =================
__global__ void k_hist(const int* __restrict__ dst) {
    int e = blockIdx.x * blockDim.x + threadIdx.x;
    if (e >= ET) return;
    int d = (e < EE) ? dst[e] : (e - EE);
    atomicAdd(&g_deg[d], 1);
}

__global__ void k_scan_block() {
    __shared__ int sm[256];
    int t = threadIdx.x;
    int i = blockIdx.x * 256 + t;
    int v = (i < NN) ? g_deg[i] : 0;
    sm[t] = v;
    __syncthreads();
#pragma unroll
    for (int off = 1; off < 256; off <<= 1) {
        int u = (t >= off) ? sm[t - off] : 0;
        __syncthreads();
        sm[t] += u;
        __syncthreads();
    }
    if (i < NN) g_tmp[i] = sm[t] - v;       // exclusive within block
    if (t == 255) g_part[blockIdx.x] = sm[255];
}

__global__ void k_scan_part() {
    __shared__ int sm[512];
    int t = threadIdx.x;
    int v = (t < NBLK) ? g_part[t] : 0;
    sm[t] = v;
    __syncthreads();
#pragma unroll
    for (int off = 1; off < 512; off <<= 1) {
        int u = (t >= off) ? sm[t - off] : 0;
        __syncthreads();
        sm[t] += u;
        __syncthreads();
    }
    if (t < NBLK) g_part[t] = sm[t] - v;    // exclusive
}

__global__ void k_scan_add() {
    int i = blockIdx.x * blockDim.x + threadIdx.x;
    if (i < NN) {
        int r = g_tmp[i] + g_part[i >> 8];
        g_row[i] = r;
        g_cursor[i] = r;
    }
    if (i == 0) g_row[NN] = ET;
}

__global__ void k_scatter(const int* __restrict__ src, const int* __restrict__ dst) {
    int e = blockIdx.x * blockDim.x + threadIdx.x;
    if (e >= ET) return;
    int s, d;
    if (e < EE) { s = src[e]; d = dst[e]; } else { s = d = e - EE; }
    int pos = atomicAdd(&g_cursor[d], 1);
    g_csr_src[pos] = s;
}

// ================= GEMM + fused alpha epilogue =================
// C[N,64] = A[N,DIN] @ W[DIN,64]; also as/ad = C . a_src / a_dst per row.
// 64x64 tile, BK=16, blockDim (16,16), 4x4 micro-tile, packed f32x2 FMA.
template <int DIN>
__global__ void k_gemm(const float* __restrict__ A, const float* __restrict__ W,
                       const float* __restrict__ asrc, const float* __restrict__ adst) {
    __shared__ float2 As2[16][66];   // duplicated pairs {a,a}
    __shared__ float  Bs[16][64];

    const float* Ap = A ? A : g_act;
    int tx = threadIdx.x, ty = threadIdx.y;
    int tid = ty * 16 + tx;
    int row0 = blockIdx.x * 64;

    int lr = tid >> 2, lq = tid & 3;   // A loader: row, float4 slot
    int bk = tid >> 4, bq = tid & 15;  // B loader: k row, float4 slot

    unsigned long long acc[4][2] = {};   // 4 rows x 4 cols (as 2 f32x2)

    for (int k0 = 0; k0 < DIN; k0 += 16) {
        int ar = row0 + lr;
        float4 av = make_float4(0.f, 0.f, 0.f, 0.f);
        if (ar < NN) av = *(const float4*)(Ap + (size_t)ar * DIN + k0 + lq * 4);
        As2[lq * 4 + 0][lr] = make_float2(av.x, av.x);
        As2[lq * 4 + 1][lr] = make_float2(av.y, av.y);
        As2[lq * 4 + 2][lr] = make_float2(av.z, av.z);
        As2[lq * 4 + 3][lr] = make_float2(av.w, av.w);

        float4 bv = *(const float4*)(W + (size_t)(k0 + bk) * 64 + bq * 4);
        *(float4*)(&Bs[bk][bq * 4]) = bv;
        __syncthreads();

#pragma unroll
        for (int k = 0; k < 16; k++) {
            float4 b = *(float4*)(&Bs[k][tx * 4]);
            unsigned long long b01 = pk2(b.x, b.y);
            unsigned long long b23 = pk2(b.z, b.w);
            unsigned long long a01[2], a23[2];
            *(float4*)a01 = *(float4*)(&As2[k][ty * 4 + 0]);
            *(float4*)a23 = *(float4*)(&As2[k][ty * 4 + 2]);
            fma2(acc[0][0], a01[0], b01); fma2(acc[0][1], a01[0], b23);
            fma2(acc[1][0], a01[1], b01); fma2(acc[1][1], a01[1], b23);
            fma2(acc[2][0], a23[0], b01); fma2(acc[2][1], a23[0], b23);
            fma2(acc[3][0], a23[1], b01); fma2(acc[3][1], a23[1], b23);
        }
        __syncthreads();
    }

    // epilogue: store h and reduce alpha dot-products across the 16-lane segment
    float4 asv = ((const float4*)asrc)[tx];
    float4 adv = ((const float4*)adst)[tx];
    unsigned seg_mask = 0xFFFFu << ((ty & 1) * 16);

#pragma unroll
    for (int i = 0; i < 4; i++) {
        int r = row0 + ty * 4 + i;
        float4 v;
        unpk2(acc[i][0], v.x, v.y);
        unpk2(acc[i][1], v.z, v.w);
        if (r < NN)
            *(float4*)(g_h + (size_t)r * 64 + tx * 4) = v;

        float s = v.x * asv.x + v.y * asv.y + v.z * asv.z + v.w * asv.w;
        float d = v.x * adv.x + v.y * adv.y + v.z * adv.z + v.w * adv.w;
#pragma unroll
        for (int o = 8; o; o >>= 1) {
            s += __shfl_xor_sync(seg_mask, s, o, 16);
            d += __shfl_xor_sync(seg_mask, d, o, 16);
        }
        if (tx == 0 && r < NN) { g_as[r] = s; g_ad[r] = d; }
    }
}

// ================= fused GAT aggregation: 16 lanes per dst node =================
// softmax over incoming edges + weighted sum of h[src] + bias + relu, no atomics.
__global__ void k_gat_agg(const float* __restrict__ b) {
    int t = blockIdx.x * blockDim.x + threadIdx.x;
    int node = t >> 4;
    int ln = threadIdx.x & 15;
    if (node >= NN) return;
    unsigned seg_mask = 0xFFFFu << (threadIdx.x & 16);

    int row = g_row[node], end = g_row[node + 1];
    int deg = end - row;
    float ad = g_ad[node];

    // scores + segment max (cache per-lane score/src for deg<=16)
    float m = -CUDART_INF_F;
    float myv = 0.f; int mys = 0;
    for (int i = row + ln; i < end; i += 16) {
        int s = g_csr_src[i];
        float v = g_as[s] + ad;
        v = fmaxf(v, 0.2f * v);          // leaky_relu(0.2)
        mys = s; myv = v;
        m = fmaxf(m, v);
    }
#pragma unroll
    for (int o = 8; o; o >>= 1) m = fmaxf(m, __shfl_xor_sync(seg_mask, m, o, 16));

    float den = 0.f;
    unsigned long long acc01 = 0, acc23 = 0;   // this lane's float4 of the output row

    if (deg <= 16) {
        float num = 0.f; int s = 0;
        if (ln < deg) { num = __expf(myv - m); s = mys; }
        den = num;
#pragma unroll 4
        for (int j = 0; j < deg; j++) {
            float c = __shfl_sync(seg_mask, num, j, 16);
            int  ss = __shfl_sync(seg_mask, s, j, 16);
            float4 hv = *((const float4*)(g_h + (size_t)ss * 64) + ln);
            unsigned long long cc = pk2(c, c);
            fma2(acc01, pk2(hv.x, hv.y), cc);
            fma2(acc23, pk2(hv.z, hv.w), cc);
        }
    } else {
        for (int base = row; base < end; base += 16) {
            int i = base + ln;
            int s = 0; float num = 0.f;
            if (i < end) {
                s = g_csr_src[i];
                float v = g_as[s] + ad;
                v = fmaxf(v, 0.2f * v);
                num = __expf(v - m);
            }
            den += num;
            int cnt = min(16, end - base);
            for (int j = 0; j < cnt; j++) {
                float c = __shfl_sync(seg_mask, num, j, 16);
                int  ss = __shfl_sync(seg_mask, s, j, 16);
                float4 hv = *((const float4*)(g_h + (size_t)ss * 64) + ln);
                unsigned long long cc = pk2(c, c);
                fma2(acc01, pk2(hv.x, hv.y), cc);
                fma2(acc23, pk2(hv.z, hv.w), cc);
            }
        }
    }
#pragma unroll
    for (int o = 8; o; o >>= 1) den += __shfl_xor_sync(seg_mask, den, o, 16);

    float inv = 1.f / (den + 1e-16f);
    float4 a, b4 = ((const float4*)b)[ln];
    unpk2(acc01, a.x, a.y);
    unpk2(acc23, a.z, a.w);
    float4 o4;
    o4.x = fmaxf(a.x * inv + b4.x, 0.f);
    o4.y = fmaxf(a.y * inv + b4.y, 0.f);
    o4.z = fmaxf(a.z * inv + b4.z, 0.f);
    o4.w = fmaxf(a.w * inv + b4.w, 0.f);
    *((float4*)(g_act + (size_t)node * 64) + ln) = o4;
}

// ================= pooling / head =================
__global__ void k_pool(const int* __restrict__ batch) {
    int n0 = blockIdx.x * 128;
    int c = threadIdx.x;          // 0..63
    int nend = min(n0 + 128, NN);
    float cur = 0.f; int curg = -1;
    for (int n = n0 + threadIdx.y; n < nend; n += 4) {
        int g = batch[n];
        float v = g_act[(size_t)n * 64 + c];
        if (g != curg) {
            if (curg >= 0) atomicMaxF(&g_pool[curg * 64 + c], cur);
            curg = g; cur = v;
        } else {
            cur = fmaxf(cur, v);
        }
    }
    if (curg >= 0) atomicMaxF(&g_pool[curg * 64 + c], cur);
}

__global__ void k_root(const int* __restrict__ batch) {
    int i = blockIdx.x * blockDim.x + threadIdx.x;
    if (i >= NN) return;
    int g = batch[i];
    if (i == 0 || batch[i - 1] != g) atomicMin(&g_root[g], i);
}

__global__ void k_head(const float* __restrict__ x,
                       const float* __restrict__ lnW, const float* __restrict__ lnb,
                       const float* __restrict__ l0W, const float* __restrict__ l0b,
                       const float* __restrict__ l1W, const float* __restrict__ l1b,
                       float* __restrict__ out) {
    int g = blockIdx.x;
    int c = threadIdx.x;   // 0..63
    __shared__ float red[2];

    float acc = l0b[c];
#pragma unroll 8
    for (int k = 0; k < 64; k++) acc += g_pool[g * 64 + k] * l0W[k * 64 + c];
    float hp = fmaxf(acc, 0.f);

    const float* xr = x + (size_t)g_root[g] * DIN0;
    float accn = lnb[c];
#pragma unroll 8
    for (int k = 0; k < 128; k++) accn += xr[k] * lnW[k * 64 + c];
    float nw = fmaxf(accn, 0.f);

    float p = hp * l1W[c] + nw * l1W[64 + c];
#pragma unroll
    for (int o = 16; o; o >>= 1) p += __shfl_xor_sync(0xFFFFFFFFu, p, o);
    if ((c & 31) == 0) red[c >> 5] = p;
    __syncthreads();
    if (c == 0) {
        float z = red[0] + red[1] + l1b[0];
        out[g] = 1.f / (1.f + __expf(-z));
    }
}

// ================= launch =================
extern "C" void kernel_launch(void* const* d_in, const int* in_sizes, int n_in,
                              void* d_out, int out_size) {
    const float* x      = (const float*)d_in[0];
    const int*   adj    = (const int*)d_in[1];
    const int*   batch  = (const int*)d_in[2];
    const float* W1     = (const float*)d_in[3];
    const float* asrc1  = (const float*)d_in[4];
    const float* adst1  = (const float*)d_in[5];
    const float* b1     = (const float*)d_in[6];
    const float* W2     = (const float*)d_in[7];
    const float* asrc2  = (const float*)d_in[8];
    const float* adst2  = (const float*)d_in[9];
    const float* b2     = (const float*)d_in[10];
    const float* W3     = (const float*)d_in[11];
    const float* asrc3  = (const float*)d_in[12];
    const float* adst3  = (const float*)d_in[13];
    const float* b3     = (const float*)d_in[14];
    const float* lnW    = (const float*)d_in[15];
    const float* lnb    = (const float*)d_in[16];
    const float* l0W    = (const float*)d_in[17];
    const float* l0b    = (const float*)d_in[18];
    const float* l1W    = (const float*)d_in[19];
    const float* l1b    = (const float*)d_in[20];
    float* out = (float*)d_out;

    const int* src = adj;
    const int* dst = adj + EE;

    void* p_deg = nullptr; void* p_pool = nullptr; void* p_root = nullptr;
    cudaGetSymbolAddress(&p_deg,  g_deg);
    cudaGetSymbolAddress(&p_pool, g_pool);
    cudaGetSymbolAddress(&p_root, g_root);

    const int GEMM_GRID  = (NN + 63) / 64;            // 1563
    const dim3 GEMM_BLK(16, 16);
    const int EDGE_GRID  = (ET + 255) / 256;          // 4297
    const int AGG_GRID   = (NN * 16 + 255) / 256;     // 6250 (16 lanes per node)

    // ---- build dst-CSR once (reused by all 3 layers) ----
    cudaMemsetAsync(p_deg, 0, NN * sizeof(int));
    k_hist<<<EDGE_GRID, 256>>>(dst);
    k_scan_block<<<NBLK, 256>>>();
    k_scan_part<<<1, 512>>>();
    k_scan_add<<<NBLK, 256>>>();
    k_scatter<<<EDGE_GRID, 256>>>(src, dst);

    // ---- layer 1 (DIN=128, input x) ----
    k_gemm<128><<<GEMM_GRID, GEMM_BLK>>>(x, W1, asrc1, adst1);
    k_gat_agg<<<AGG_GRID, 256>>>(b1);

    // ---- layer 2 (DIN=64, input g_act via nullptr) ----
    k_gemm<64><<<GEMM_GRID, GEMM_BLK>>>(nullptr, W2, asrc2, adst2);
    k_gat_agg<<<AGG_GRID, 256>>>(b2);

    // ---- layer 3 ----
    k_gemm<64><<<GEMM_GRID, GEMM_BLK>>>(nullptr, W3, asrc3, adst3);
    k_gat_agg<<<AGG_GRID, 256>>>(b3);

    // ---- head ----
    cudaMemsetAsync(p_pool, 0xFF, GG * HH * sizeof(float));   // -NaN bits: valid floor for atomicMaxF
    cudaMemsetAsync(p_root, 0x7F, GG * sizeof(int));          // 0x7F7F7F7F > NN
    k_pool<<<(NN + 127) / 128, dim3(64, 4)>>>(batch);
    k_root<<<(NN + 255) / 256, 256>>>(batch);
    k_head<<<GG, 64>>>(x, lnW, lnb, l0W, l0b, l1W, l1b, out);
}

// round 7
// speedup vs baseline: 1.6323x; 1.0470x over previous
#include <cuda_runtime.h>
#include <cuda_bf16.h>
#include <math_constants.h>

// Problem constants
#define NN 100000
#define EE 1000000
#define ET (NN + EE)        // edges incl. self-loops = 1,100,000
#define GG 64
#define HH 64
#define DIN0 128
#define NBLK ((NN + 255) / 256)   // 391

// ---------------- device scratch (no allocations allowed) ----------------
__device__ float g_h[(size_t)NN * HH];      // h = x @ W (pre-bias)
__device__ float g_act[(size_t)NN * HH];    // relu(agg + b) -> next layer input
__device__ float g_as[NN];                  // h . a_src per node
__device__ float g_ad[NN];                  // h . a_dst per node
__device__ float g_pool[GG * HH];
__device__ int   g_root[GG];

// CSR by dst (rebuilt every call; graph static across layers)
__device__ int g_deg[NN];
__device__ int g_tmp[NN];          // block-local exclusive scan
__device__ int g_part[NBLK];       // per-block sums
__device__ int g_row[NN + 1];
__device__ int g_cursor[NN];
__device__ int g_csr_src[ET];

// ---------------- helpers ----------------
__device__ __forceinline__ void atomicMaxF(float* addr, float v) {
    if (v >= 0.f) atomicMax((int*)addr, __float_as_int(v));
    else          atomicMin((unsigned int*)addr, __float_as_uint(v));
}

__device__ __forceinline__ unsigned long long pk2(float lo, float hi) {
    unsigned long long r;
    asm("mov.b64 %0, {%1,%2};" : "=l"(r) : "f"(lo), "f"(hi));
    return r;
}
__device__ __forceinline__ void unpk2(unsigned long long v, float& lo, float& hi) {
    asm("mov.b64 {%0,%1}, %2;" : "=f"(lo), "=f"(hi) : "l"(v));
}
__device__ __forceinline__ void fma2(unsigned long long& acc, unsigned long long a,
                                     unsigned long long b) {
    asm("fma.rn.f32x2 %0, %1, %2, %0;" : "+l"(acc) : "l"(a), "l"(b));
}

// ================= CSR build =================
__global__ void k_hist(const int* __restrict__ dst) {
    int e = blockIdx.x * blockDim.x + threadIdx.x;
    if (e >= ET) return;
    int d = (e < EE) ? dst[e] : (e - EE);
    atomicAdd(&g_deg[d], 1);
}

__global__ void k_scan_block() {
    __shared__ int sm[256];
    int t = threadIdx.x;
    int i = blockIdx.x * 256 + t;
    int v = (i < NN) ? g_deg[i] : 0;
    sm[t] = v;
    __syncthreads();
#pragma unroll
    for (int off = 1; off < 256; off <<= 1) {
        int u = (t >= off) ? sm[t - off] : 0;
        __syncthreads();
        sm[t] += u;
        __syncthreads();
    }
    if (i < NN) g_tmp[i] = sm[t] - v;       // exclusive within block
    if (t == 255) g_part[blockIdx.x] = sm[255];
}

// fused: per-block prefix of g_part + final add (replaces scan_part + scan_add)
__global__ void k_scan_add() {
    __shared__ int s_sum;
    int t = threadIdx.x, bid = blockIdx.x;
    if (t == 0) s_sum = 0;
    __syncthreads();
    int v = 0;
    for (int j = t; j < bid; j += 256) v += g_part[j];
#pragma unroll
    for (int o = 16; o; o >>= 1) v += __shfl_xor_sync(0xFFFFFFFFu, v, o);
    if ((t & 31) == 0 && v) atomicAdd(&s_sum, v);
    __syncthreads();
    int i = bid * 256 + t;
    if (i < NN) {
        int r = g_tmp[i] + s_sum;
        g_row[i] = r;
        g_cursor[i] = r;
    }
    if (i == 0) g_row[NN] = ET;
}

__global__ void k_scatter(const int* __restrict__ src, const int* __restrict__ dst) {
    int e = blockIdx.x * blockDim.x + threadIdx.x;
    if (e >= ET) return;
    int s, d;
    if (e < EE) { s = src[e]; d = dst[e]; } else { s = d = e - EE; }
    int pos = atomicAdd(&g_cursor[d], 1);
    g_csr_src[pos] = s;
}

// ================= GEMM + fused alpha epilogue =================
// C[N,64] = A[N,DIN] @ W[DIN,64]; also as/ad = C . a_src / a_dst per row.
// 128x64 tile, BK=16, blockDim (16,16), 8x4 micro-tile, packed f32x2 FMA.
template <int DIN>
__global__ void k_gemm(const float* __restrict__ A, const float* __restrict__ W,
                       const float* __restrict__ asrc, const float* __restrict__ adst) {
    __shared__ float2 As2[16][130];   // duplicated pairs {a,a}; even stride keeps 16B align
    __shared__ float  Bs[16][64];

    const float* Ap = A ? A : g_act;
    int tx = threadIdx.x, ty = threadIdx.y;
    int tid = ty * 16 + tx;
    int row0 = blockIdx.x * 128;

    // A loader: each thread owns one tile row, two float4s at k-offsets
    // q0*4 and q0*4+8 (q0 = tid&1). Odd/even lanes hit different k-rows so
    // the duplicated STS.64s land on the 2-phase crossbar floor.
    int arow = tid >> 1;
    int q0 = (tid & 1) * 4;          // 0 or 4
    // B loader
    int bk = tid >> 4, bq = tid & 15;

    unsigned long long acc[8][2] = {};   // 8 rows x 4 cols (as 2 f32x2)

    for (int k0 = 0; k0 < DIN; k0 += 16) {
        int ar = row0 + arow;
        float4 av0 = make_float4(0.f, 0.f, 0.f, 0.f);
        float4 av1 = make_float4(0.f, 0.f, 0.f, 0.f);
        if (ar < NN) {
            const float* ap = Ap + (size_t)ar * DIN + k0;
            av0 = *(const float4*)(ap + q0);
            av1 = *(const float4*)(ap + q0 + 8);
        }
        As2[q0 + 0][arow]  = make_float2(av0.x, av0.x);
        As2[q0 + 1][arow]  = make_float2(av0.y, av0.y);
        As2[q0 + 2][arow]  = make_float2(av0.z, av0.z);
        As2[q0 + 3][arow]  = make_float2(av0.w, av0.w);
        As2[q0 + 8][arow]  = make_float2(av1.x, av1.x);
        As2[q0 + 9][arow]  = make_float2(av1.y, av1.y);
        As2[q0 + 10][arow] = make_float2(av1.z, av1.z);
        As2[q0 + 11][arow] = make_float2(av1.w, av1.w);

        float4 bv = *(const float4*)(W + (size_t)(k0 + bk) * 64 + bq * 4);
        *(float4*)(&Bs[bk][bq * 4]) = bv;
        __syncthreads();

#pragma unroll
        for (int k = 0; k < 16; k++) {
            float4 b = *(float4*)(&Bs[k][tx * 4]);
            unsigned long long b01 = pk2(b.x, b.y);
            unsigned long long b23 = pk2(b.z, b.w);
            unsigned long long a[4][2];
            *(float4*)a[0] = *(float4*)(&As2[k][ty * 8 + 0]);
            *(float4*)a[1] = *(float4*)(&As2[k][ty * 8 + 2]);
            *(float4*)a[2] = *(float4*)(&As2[k][ty * 8 + 4]);
            *(float4*)a[3] = *(float4*)(&As2[k][ty * 8 + 6]);
#pragma unroll
            for (int r = 0; r < 8; r++) {
                fma2(acc[r][0], a[r >> 1][r & 1], b01);
                fma2(acc[r][1], a[r >> 1][r & 1], b23);
            }
        }
        __syncthreads();
    }

    // epilogue: store h and reduce alpha dot-products across the 16-lane segment
    float4 asv = ((const float4*)asrc)[tx];
    float4 adv = ((const float4*)adst)[tx];
    unsigned seg_mask = 0xFFFFu << ((ty & 1) * 16);

#pragma unroll
    for (int i = 0; i < 8; i++) {
        int r = row0 + ty * 8 + i;
        float4 v;
        unpk2(acc[i][0], v.x, v.y);
        unpk2(acc[i][1], v.z, v.w);
        if (r < NN)
            *(float4*)(g_h + (size_t)r * 64 + tx * 4) = v;

        float s = v.x * asv.x + v.y * asv.y + v.z * asv.z + v.w * asv.w;
        float d = v.x * adv.x + v.y * adv.y + v.z * adv.z + v.w * adv.w;
#pragma unroll
        for (int o = 8; o; o >>= 1) {
            s += __shfl_xor_sync(seg_mask, s, o, 16);
            d += __shfl_xor_sync(seg_mask, d, o, 16);
        }
        if (tx == 0 && r < NN) { g_as[r] = s; g_ad[r] = d; }
    }
}

// ================= fused GAT aggregation: 16 lanes per dst node =================
__global__ void k_gat_agg(const float* __restrict__ b) {
    int t = blockIdx.x * blockDim.x + threadIdx.x;
    int node = t >> 4;
    int ln = threadIdx.x & 15;
    if (node >= NN) return;
    unsigned seg_mask = 0xFFFFu << (threadIdx.x & 16);

    int row = g_row[node], end = g_row[node + 1];
    int deg = end - row;
    float ad = g_ad[node];

    // scores + segment max (cache per-lane score/src for deg<=16)
    float m = -CUDART_INF_F;
    float myv = 0.f; int mys = 0;
    for (int i = row + ln; i < end; i += 16) {
        int s = g_csr_src[i];
        float v = g_as[s] + ad;
        v = fmaxf(v, 0.2f * v);          // leaky_relu(0.2)
        mys = s; myv = v;
        m = fmaxf(m, v);
    }
#pragma unroll
    for (int o = 8; o; o >>= 1) m = fmaxf(m, __shfl_xor_sync(seg_mask, m, o, 16));

    float den = 0.f;
    unsigned long long acc01 = 0, acc23 = 0;   // this lane's float4 of the output row

    if (deg <= 16) {
        float num = 0.f; int s = 0;
        if (ln < deg) { num = __expf(myv - m); s = mys; }
        den = num;
#pragma unroll 4
        for (int j = 0; j < deg; j++) {
            float c = __shfl_sync(seg_mask, num, j, 16);
            int  ss = __shfl_sync(seg_mask, s, j, 16);
            float4 hv = *((const float4*)(g_h + (size_t)ss * 64) + ln);
            unsigned long long cc = pk2(c, c);
            fma2(acc01, pk2(hv.x, hv.y), cc);
            fma2(acc23, pk2(hv.z, hv.w), cc);
        }
    } else {
        for (int base = row; base < end; base += 16) {
            int i = base + ln;
            int s = 0; float num = 0.f;
            if (i < end) {
                s = g_csr_src[i];
                float v = g_as[s] + ad;
                v = fmaxf(v, 0.2f * v);
                num = __expf(v - m);
            }
            den += num;
            int cnt = min(16, end - base);
            for (int j = 0; j < cnt; j++) {
                float c = __shfl_sync(seg_mask, num, j, 16);
                int  ss = __shfl_sync(seg_mask, s, j, 16);
                float4 hv = *((const float4*)(g_h + (size_t)ss * 64) + ln);
                unsigned long long cc = pk2(c, c);
                fma2(acc01, pk2(hv.x, hv.y), cc);
                fma2(acc23, pk2(hv.z, hv.w), cc);
            }
        }
    }
#pragma unroll
    for (int o = 8; o; o >>= 1) den += __shfl_xor_sync(seg_mask, den, o, 16);

    float inv = 1.f / (den + 1e-16f);
    float4 a, b4 = ((const float4*)b)[ln];
    unpk2(acc01, a.x, a.y);
    unpk2(acc23, a.z, a.w);
    float4 o4;
    o4.x = fmaxf(a.x * inv + b4.x, 0.f);
    o4.y = fmaxf(a.y * inv + b4.y, 0.f);
    o4.z = fmaxf(a.z * inv + b4.z, 0.f);
    o4.w = fmaxf(a.w * inv + b4.w, 0.f);
    *((float4*)(g_act + (size_t)node * 64) + ln) = o4;
}

// ================= pooling (with fused root detection) / head =================
__global__ void k_pool(const int* __restrict__ batch) {
    int n0 = blockIdx.x * 128;
    int c = threadIdx.x;          // 0..63
    int nend = min(n0 + 128, NN);
    float cur = 0.f; int curg = -1;
    for (int n = n0 + threadIdx.y; n < nend; n += 4) {
        int g = batch[n];
        if (c == 0) {             // root detection: first index of each graph
            if (n == 0 || batch[n - 1] != g) atomicMin(&g_root[g], n);
        }
        float v = g_act[(size_t)n * 64 + c];
        if (g != curg) {
            if (curg >= 0) atomicMaxF(&g_pool[curg * 64 + c], cur);
            curg = g; cur = v;
        } else {
            cur = fmaxf(cur, v);
        }
    }
    if (curg >= 0) atomicMaxF(&g_pool[curg * 64 + c], cur);
}

__global__ void k_head(const float* __restrict__ x,
                       const float* __restrict__ lnW, const float* __restrict__ lnb,
                       const float* __restrict__ l0W, const float* __restrict__ l0b,
                       const float* __restrict__ l1W, const float* __restrict__ l1b,
                       float* __restrict__ out) {
    int g = blockIdx.x;
    int c = threadIdx.x;   // 0..63
    __shared__ float red[2];

    float acc = l0b[c];
#pragma unroll 8
    for (int k = 0; k < 64; k++) acc += g_pool[g * 64 + k] * l0W[k * 64 + c];
    float hp = fmaxf(acc, 0.f);

    const float* xr = x + (size_t)g_root[g] * DIN0;
    float accn = lnb[c];
#pragma unroll 8
    for (int k = 0; k < 128; k++) accn += xr[k] * lnW[k * 64 + c];
    float nw = fmaxf(accn, 0.f);

    float p = hp * l1W[c] + nw * l1W[64 + c];
#pragma unroll
    for (int o = 16; o; o >>= 1) p += __shfl_xor_sync(0xFFFFFFFFu, p, o);
    if ((c & 31) == 0) red[c >> 5] = p;
    __syncthreads();
    if (c == 0) {
        float z = red[0] + red[1] + l1b[0];
        out[g] = 1.f / (1.f + __expf(-z));
    }
}

// ================= launch =================
extern "C" void kernel_launch(void* const* d_in, const int* in_sizes, int n_in,
                              void* d_out, int out_size) {
    const float* x      = (const float*)d_in[0];
    const int*   adj    = (const int*)d_in[1];
    const int*   batch  = (const int*)d_in[2];
    const float* W1     = (const float*)d_in[3];
    const float* asrc1  = (const float*)d_in[4];
    const float* adst1  = (const float*)d_in[5];
    const float* b1     = (const float*)d_in[6];
    const float* W2     = (const float*)d_in[7];
    const float* asrc2  = (const float*)d_in[8];
    const float* adst2  = (const float*)d_in[9];
    const float* b2     = (const float*)d_in[10];
    const float* W3     = (const float*)d_in[11];
    const float* asrc3  = (const float*)d_in[12];
    const float* adst3  = (const float*)d_in[13];
    const float* b3     = (const float*)d_in[14];
    const float* lnW    = (const float*)d_in[15];
    const float* lnb    = (const float*)d_in[16];
    const float* l0W    = (const float*)d_in[17];
    const float* l0b    = (const float*)d_in[18];
    const float* l1W    = (const float*)d_in[19];
    const float* l1b    = (const float*)d_in[20];
    float* out = (float*)d_out;

    const int* src = adj;
    const int* dst = adj + EE;

    void* p_deg = nullptr; void* p_pool = nullptr; void* p_root = nullptr;
    cudaGetSymbolAddress(&p_deg,  g_deg);
    cudaGetSymbolAddress(&p_pool, g_pool);
    cudaGetSymbolAddress(&p_root, g_root);

    const int GEMM_GRID  = (NN + 127) / 128;          // 782
    const dim3 GEMM_BLK(16, 16);
    const int EDGE_GRID  = (ET + 255) / 256;          // 4297
    const int AGG_GRID   = (NN * 16 + 255) / 256;     // 6250 (16 lanes per node)

    // ---- CSR build (launch order puts gemm1 at kernel #4 for profiling) ----
    cudaMemsetAsync(p_deg, 0, NN * sizeof(int));
    k_hist<<<EDGE_GRID, 256>>>(dst);                              // 1
    k_scan_block<<<NBLK, 256>>>();                                // 2
    k_scan_add<<<NBLK, 256>>>();                                  // 3
    k_gemm<128><<<GEMM_GRID, GEMM_BLK>>>(x, W1, asrc1, adst1);    // 4 <- profiled
    k_scatter<<<EDGE_GRID, 256>>>(src, dst);                      // 5
    k_gat_agg<<<AGG_GRID, 256>>>(b1);                             // 6

    // ---- layer 2 / 3 ----
    k_gemm<64><<<GEMM_GRID, GEMM_BLK>>>(nullptr, W2, asrc2, adst2);
    k_gat_agg<<<AGG_GRID, 256>>>(b2);
    k_gemm<64><<<GEMM_GRID, GEMM_BLK>>>(nullptr, W3, asrc3, adst3);
    k_gat_agg<<<AGG_GRID, 256>>>(b3);

    // ---- head ----
    cudaMemsetAsync(p_pool, 0xFF, GG * HH * sizeof(float));   // -NaN bits: valid floor for atomicMaxF
    cudaMemsetAsync(p_root, 0x7F, GG * sizeof(int));          // 0x7F7F7F7F > NN
    k_pool<<<(NN + 127) / 128, dim3(64, 4)>>>(batch);
    k_head<<<GG, 64>>>(x, lnW, lnb, l0W, l0b, l1W, l1b, out);
}

// round 8
// speedup vs baseline: 1.6937x; 1.0376x over previous
#include <cuda_runtime.h>
#include <cuda_bf16.h>
#include <math_constants.h>

// Problem constants
#define NN 100000
#define EE 1000000
#define ET (NN + EE)        // edges incl. self-loops = 1,100,000
#define GG 64
#define HH 64
#define DIN0 128
#define NBLK ((NN + 255) / 256)   // 391

// ---------------- device scratch (no allocations allowed) ----------------
__device__ float g_h[(size_t)NN * HH];      // h = x @ W (pre-bias)
__device__ float g_act[(size_t)NN * HH];    // relu(agg + b) -> next layer input
__device__ float g_as[NN];                  // h . a_src per node
__device__ float g_ad[NN];                  // h . a_dst per node
__device__ float g_pool[GG * HH];
__device__ int   g_root[GG];

// CSR by dst (rebuilt every call; graph static across layers)
__device__ int g_deg[NN];
__device__ int g_tmp[NN];          // block-local exclusive scan
__device__ int g_part[NBLK];       // per-block sums
__device__ int g_row[NN + 1];
__device__ int g_cursor[NN];
__device__ int g_csr_src[ET];

// ---------------- helpers ----------------
__device__ __forceinline__ void atomicMaxF(float* addr, float v) {
    if (v >= 0.f) atomicMax((int*)addr, __float_as_int(v));
    else          atomicMin((unsigned int*)addr, __float_as_uint(v));
}

__device__ __forceinline__ unsigned long long pk2(float lo, float hi) {
    unsigned long long r;
    asm("mov.b64 %0, {%1,%2};" : "=l"(r) : "f"(lo), "f"(hi));
    return r;
}
__device__ __forceinline__ void unpk2(unsigned long long v, float& lo, float& hi) {
    asm("mov.b64 {%0,%1}, %2;" : "=f"(lo), "=f"(hi) : "l"(v));
}
__device__ __forceinline__ void fma2(unsigned long long& acc, unsigned long long a,
                                     unsigned long long b) {
    asm("fma.rn.f32x2 %0, %1, %2, %0;" : "+l"(acc) : "l"(a), "l"(b));
}

// ================= CSR build =================
__global__ void k_hist(const int* __restrict__ dst) {
    int e = blockIdx.x * blockDim.x + threadIdx.x;
    if (e >= ET) return;
    int d = (e < EE) ? dst[e] : (e - EE);
    atomicAdd(&g_deg[d], 1);
}

__global__ void k_scan_block() {
    __shared__ int sm[256];
    int t = threadIdx.x;
    int i = blockIdx.x * 256 + t;
    int v = (i < NN) ? g_deg[i] : 0;
    sm[t] = v;
    __syncthreads();
#pragma unroll
    for (int off = 1; off < 256; off <<= 1) {
        int u = (t >= off) ? sm[t - off] : 0;
        __syncthreads();
        sm[t] += u;
        __syncthreads();
    }
    if (i < NN) g_tmp[i] = sm[t] - v;       // exclusive within block
    if (t == 255) g_part[blockIdx.x] = sm[255];
}

// fused: per-block prefix of g_part + final add
__global__ void k_scan_add() {
    __shared__ int s_sum;
    int t = threadIdx.x, bid = blockIdx.x;
    if (t == 0) s_sum = 0;
    __syncthreads();
    int v = 0;
    for (int j = t; j < bid; j += 256) v += g_part[j];
#pragma unroll
    for (int o = 16; o; o >>= 1) v += __shfl_xor_sync(0xFFFFFFFFu, v, o);
    if ((t & 31) == 0 && v) atomicAdd(&s_sum, v);
    __syncthreads();
    int i = bid * 256 + t;
    if (i < NN) {
        int r = g_tmp[i] + s_sum;
        g_row[i] = r;
        g_cursor[i] = r;
    }
    if (i == 0) g_row[NN] = ET;
}

__global__ void k_scatter(const int* __restrict__ src, const int* __restrict__ dst) {
    int e = blockIdx.x * blockDim.x + threadIdx.x;
    if (e >= ET) return;
    int s, d;
    if (e < EE) { s = src[e]; d = dst[e]; } else { s = d = e - EE; }
    int pos = atomicAdd(&g_cursor[d], 1);
    g_csr_src[pos] = s;
}

// ================= GEMM + fused alpha epilogue =================
// C[N,64] = A[N,DIN] @ W[DIN,64]; also as/ad = C . a_src / a_dst per row.
// 256x64 tile, BK=16, 256 threads, 8x8 micro-tile (rows rg*8.., cols cg*4 & 32+cg*4),
// A un-duplicated in smem (k-major), register mov.b64 duplication, packed f32x2 FMA.
// Per-SM per k: LDS 128 cyc == fma 128 cyc (balanced at both ceilings).
template <int DIN>
__global__ void __launch_bounds__(256) k_gemm(
        const float* __restrict__ A, const float* __restrict__ W,
        const float* __restrict__ asrc, const float* __restrict__ adst) {
    __shared__ float As[16][256];    // [k][row] — warp writes 32 consecutive floats
    __shared__ float Bs[16][64];

    const float* Ap = A ? A : g_act;
    int tid = threadIdx.x;
    int rg = tid >> 3;               // 0..31 row group
    int cg = tid & 7;                // 0..7 col group
    int row0 = blockIdx.x * 256;

    int bk = tid >> 4, bq = tid & 15;   // B loader

    unsigned long long acc[8][4] = {};  // 8 rows x 8 cols (4 f32x2)

    int arow = row0 + tid;
    const float* aptr = (arow < NN) ? (Ap + (size_t)arow * DIN) : nullptr;

    for (int k0 = 0; k0 < DIN; k0 += 16) {
        // stage A: thread owns row `tid` of the tile, 16 k-values
#pragma unroll
        for (int q = 0; q < 4; q++) {
            float4 av = make_float4(0.f, 0.f, 0.f, 0.f);
            if (aptr) av = *(const float4*)(aptr + k0 + q * 4);
            As[q * 4 + 0][tid] = av.x;
            As[q * 4 + 1][tid] = av.y;
            As[q * 4 + 2][tid] = av.z;
            As[q * 4 + 3][tid] = av.w;
        }
        // stage B
        float4 bv = *(const float4*)(W + (size_t)(k0 + bk) * 64 + bq * 4);
        *(float4*)(&Bs[bk][bq * 4]) = bv;
        __syncthreads();

#pragma unroll
        for (int k = 0; k < 16; k++) {
            float4 alo = *(float4*)(&As[k][rg * 8]);
            float4 ahi = *(float4*)(&As[k][rg * 8 + 4]);
            float4 blo = *(float4*)(&Bs[k][cg * 4]);
            float4 bhi = *(float4*)(&Bs[k][32 + cg * 4]);
            unsigned long long b0 = pk2(blo.x, blo.y);
            unsigned long long b1 = pk2(blo.z, blo.w);
            unsigned long long b2 = pk2(bhi.x, bhi.y);
            unsigned long long b3 = pk2(bhi.z, bhi.w);
            float a[8] = {alo.x, alo.y, alo.z, alo.w, ahi.x, ahi.y, ahi.z, ahi.w};
#pragma unroll
            for (int r = 0; r < 8; r++) {
                unsigned long long ad = pk2(a[r], a[r]);
                fma2(acc[r][0], ad, b0);
                fma2(acc[r][1], ad, b1);
                fma2(acc[r][2], ad, b2);
                fma2(acc[r][3], ad, b3);
            }
        }
        __syncthreads();
    }

    // epilogue: store h (cols cg*4..+4 and 32+cg*4..+4), reduce alpha over 8-lane seg
    float4 aslo = *(const float4*)(asrc + cg * 4);
    float4 ashi = *(const float4*)(asrc + 32 + cg * 4);
    float4 adlo = *(const float4*)(adst + cg * 4);
    float4 adhi = *(const float4*)(adst + 32 + cg * 4);
    int lane = tid & 31;
    unsigned seg_mask = 0xFFu << (lane & 24);

#pragma unroll
    for (int i = 0; i < 8; i++) {
        int r = row0 + rg * 8 + i;
        float4 vlo, vhi;
        unpk2(acc[i][0], vlo.x, vlo.y);
        unpk2(acc[i][1], vlo.z, vlo.w);
        unpk2(acc[i][2], vhi.x, vhi.y);
        unpk2(acc[i][3], vhi.z, vhi.w);
        if (r < NN) {
            float* hp = g_h + (size_t)r * 64;
            *(float4*)(hp + cg * 4)      = vlo;
            *(float4*)(hp + 32 + cg * 4) = vhi;
        }
        float s = vlo.x * aslo.x + vlo.y * aslo.y + vlo.z * aslo.z + vlo.w * aslo.w
                + vhi.x * ashi.x + vhi.y * ashi.y + vhi.z * ashi.z + vhi.w * ashi.w;
        float d = vlo.x * adlo.x + vlo.y * adlo.y + vlo.z * adlo.z + vlo.w * adlo.w
                + vhi.x * adhi.x + vhi.y * adhi.y + vhi.z * adhi.z + vhi.w * adhi.w;
#pragma unroll
        for (int o = 4; o; o >>= 1) {
            s += __shfl_xor_sync(seg_mask, s, o, 8);
            d += __shfl_xor_sync(seg_mask, d, o, 8);
        }
        if (cg == 0 && r < NN) { g_as[r] = s; g_ad[r] = d; }
    }
}

// ================= fused GAT aggregation: 16 lanes per dst node =================
__global__ void k_gat_agg(const float* __restrict__ b) {
    int t = blockIdx.x * blockDim.x + threadIdx.x;
    int node = t >> 4;
    int ln = threadIdx.x & 15;
    if (node >= NN) return;
    unsigned seg_mask = 0xFFFFu << (threadIdx.x & 16);

    int row = g_row[node], end = g_row[node + 1];
    int deg = end - row;
    float ad = g_ad[node];

    // scores + segment max (cache per-lane score/src for deg<=16)
    float m = -CUDART_INF_F;
    float myv = 0.f; int mys = 0;
    for (int i = row + ln; i < end; i += 16) {
        int s = g_csr_src[i];
        float v = g_as[s] + ad;
        v = fmaxf(v, 0.2f * v);          // leaky_relu(0.2)
        mys = s; myv = v;
        m = fmaxf(m, v);
    }
#pragma unroll
    for (int o = 8; o; o >>= 1) m = fmaxf(m, __shfl_xor_sync(seg_mask, m, o, 16));

    float den = 0.f;
    unsigned long long acc01 = 0, acc23 = 0;   // this lane's float4 of the output row

    if (deg <= 16) {
        float num = 0.f; int s = 0;
        if (ln < deg) { num = __expf(myv - m); s = mys; }
        den = num;
#pragma unroll 4
        for (int j = 0; j < deg; j++) {
            float c = __shfl_sync(seg_mask, num, j, 16);
            int  ss = __shfl_sync(seg_mask, s, j, 16);
            float4 hv = *((const float4*)(g_h + (size_t)ss * 64) + ln);
            unsigned long long cc = pk2(c, c);
            fma2(acc01, pk2(hv.x, hv.y), cc);
            fma2(acc23, pk2(hv.z, hv.w), cc);
        }
    } else {
        for (int base = row; base < end; base += 16) {
            int i = base + ln;
            int s = 0; float num = 0.f;
            if (i < end) {
                s = g_csr_src[i];
                float v = g_as[s] + ad;
                v = fmaxf(v, 0.2f * v);
                num = __expf(v - m);
            }
            den += num;
            int cnt = min(16, end - base);
            for (int j = 0; j < cnt; j++) {
                float c = __shfl_sync(seg_mask, num, j, 16);
                int  ss = __shfl_sync(seg_mask, s, j, 16);
                float4 hv = *((const float4*)(g_h + (size_t)ss * 64) + ln);
                unsigned long long cc = pk2(c, c);
                fma2(acc01, pk2(hv.x, hv.y), cc);
                fma2(acc23, pk2(hv.z, hv.w), cc);
            }
        }
    }
#pragma unroll
    for (int o = 8; o; o >>= 1) den += __shfl_xor_sync(seg_mask, den, o, 16);

    float inv = 1.f / (den + 1e-16f);
    float4 a, b4 = ((const float4*)b)[ln];
    unpk2(acc01, a.x, a.y);
    unpk2(acc23, a.z, a.w);
    float4 o4;
    o4.x = fmaxf(a.x * inv + b4.x, 0.f);
    o4.y = fmaxf(a.y * inv + b4.y, 0.f);
    o4.z = fmaxf(a.z * inv + b4.z, 0.f);
    o4.w = fmaxf(a.w * inv + b4.w, 0.f);
    *((float4*)(g_act + (size_t)node * 64) + ln) = o4;
}

// ================= pooling (with fused root detection) / head =================
__global__ void k_pool(const int* __restrict__ batch) {
    int n0 = blockIdx.x * 128;
    int c = threadIdx.x;          // 0..63
    int nend = min(n0 + 128, NN);
    float cur = 0.f; int curg = -1;
    for (int n = n0 + threadIdx.y; n < nend; n += 4) {
        int g = batch[n];
        if (c == 0) {             // root detection: first index of each graph
            if (n == 0 || batch[n - 1] != g) atomicMin(&g_root[g], n);
        }
        float v = g_act[(size_t)n * 64 + c];
        if (g != curg) {
            if (curg >= 0) atomicMaxF(&g_pool[curg * 64 + c], cur);
            curg = g; cur = v;
        } else {
            cur = fmaxf(cur, v);
        }
    }
    if (curg >= 0) atomicMaxF(&g_pool[curg * 64 + c], cur);
}

__global__ void k_head(const float* __restrict__ x,
                       const float* __restrict__ lnW, const float* __restrict__ lnb,
                       const float* __restrict__ l0W, const float* __restrict__ l0b,
                       const float* __restrict__ l1W, const float* __restrict__ l1b,
                       float* __restrict__ out) {
    int g = blockIdx.x;
    int c = threadIdx.x;   // 0..63
    __shared__ float red[2];

    float acc = l0b[c];
#pragma unroll 8
    for (int k = 0; k < 64; k++) acc += g_pool[g * 64 + k] * l0W[k * 64 + c];
    float hp = fmaxf(acc, 0.f);

    const float* xr = x + (size_t)g_root[g] * DIN0;
    float accn = lnb[c];
#pragma unroll 8
    for (int k = 0; k < 128; k++) accn += xr[k] * lnW[k * 64 + c];
    float nw = fmaxf(accn, 0.f);

    float p = hp * l1W[c] + nw * l1W[64 + c];
#pragma unroll
    for (int o = 16; o; o >>= 1) p += __shfl_xor_sync(0xFFFFFFFFu, p, o);
    if ((c & 31) == 0) red[c >> 5] = p;
    __syncthreads();
    if (c == 0) {
        float z = red[0] + red[1] + l1b[0];
        out[g] = 1.f / (1.f + __expf(-z));
    }
}

// ================= launch =================
extern "C" void kernel_launch(void* const* d_in, const int* in_sizes, int n_in,
                              void* d_out, int out_size) {
    const float* x      = (const float*)d_in[0];
    const int*   adj    = (const int*)d_in[1];
    const int*   batch  = (const int*)d_in[2];
    const float* W1     = (const float*)d_in[3];
    const float* asrc1  = (const float*)d_in[4];
    const float* adst1  = (const float*)d_in[5];
    const float* b1     = (const float*)d_in[6];
    const float* W2     = (const float*)d_in[7];
    const float* asrc2  = (const float*)d_in[8];
    const float* adst2  = (const float*)d_in[9];
    const float* b2     = (const float*)d_in[10];
    const float* W3     = (const float*)d_in[11];
    const float* asrc3  = (const float*)d_in[12];
    const float* adst3  = (const float*)d_in[13];
    const float* b3     = (const float*)d_in[14];
    const float* lnW    = (const float*)d_in[15];
    const float* lnb    = (const float*)d_in[16];
    const float* l0W    = (const float*)d_in[17];
    const float* l0b    = (const float*)d_in[18];
    const float* l1W    = (const float*)d_in[19];
    const float* l1b    = (const float*)d_in[20];
    float* out = (float*)d_out;

    const int* src = adj;
    const int* dst = adj + EE;

    void* p_deg = nullptr; void* p_pool = nullptr; void* p_root = nullptr;
    cudaGetSymbolAddress(&p_deg,  g_deg);
    cudaGetSymbolAddress(&p_pool, g_pool);
    cudaGetSymbolAddress(&p_root, g_root);

    const int GEMM_GRID  = (NN + 255) / 256;          // 391
    const int EDGE_GRID  = (ET + 255) / 256;          // 4297
    const int AGG_GRID   = (NN * 16 + 255) / 256;     // 6250 (16 lanes per node)

    // ---- CSR build (launch order keeps gemm1 at kernel #4 for profiling) ----
    cudaMemsetAsync(p_deg, 0, NN * sizeof(int));
    k_hist<<<EDGE_GRID, 256>>>(dst);                          // 1
    k_scan_block<<<NBLK, 256>>>();                            // 2
    k_scan_add<<<NBLK, 256>>>();                              // 3
    k_gemm<128><<<GEMM_GRID, 256>>>(x, W1, asrc1, adst1);     // 4 <- profiled
    k_scatter<<<EDGE_GRID, 256>>>(src, dst);                  // 5
    k_gat_agg<<<AGG_GRID, 256>>>(b1);                         // 6

    // ---- layer 2 / 3 ----
    k_gemm<64><<<GEMM_GRID, 256>>>(nullptr, W2, asrc2, adst2);
    k_gat_agg<<<AGG_GRID, 256>>>(b2);
    k_gemm<64><<<GEMM_GRID, 256>>>(nullptr, W3, asrc3, adst3);
    k_gat_agg<<<AGG_GRID, 256>>>(b3);

    // ---- head ----
    cudaMemsetAsync(p_pool, 0xFF, GG * HH * sizeof(float));   // -NaN bits: valid floor for atomicMaxF
    cudaMemsetAsync(p_root, 0x7F, GG * sizeof(int));          // 0x7F7F7F7F > NN
    k_pool<<<(NN + 127) / 128, dim3(64, 4)>>>(batch);
    k_head<<<GG, 64>>>(x, lnW, lnb, l0W, l0b, l1W, l1b, out);
}

// round 9
// speedup vs baseline: 1.7139x; 1.0119x over previous
#include <cuda_runtime.h>
#include <cuda_bf16.h>
#include <math_constants.h>

// Problem constants
#define NN 100000
#define EE 1000000
#define ET (NN + EE)        // edges incl. self-loops = 1,100,000
#define GG 64
#define HH 64
#define DIN0 128
#define NBLK ((NN + 255) / 256)   // 391

// ---------------- device scratch (no allocations allowed) ----------------
__device__ float g_h[(size_t)NN * HH];      // h = x @ W (pre-bias)
__device__ float g_act[(size_t)NN * HH];    // relu(agg + b) -> next layer input
__device__ float g_as[NN];                  // h . a_src per node
__device__ float g_ad[NN];                  // h . a_dst per node
__device__ float g_pool[GG * HH];
__device__ int   g_root[GG];

// CSR by dst (rebuilt every call; graph static across layers)
__device__ int g_deg[NN];
__device__ int g_tmp[NN];          // block-local exclusive scan
__device__ int g_part[NBLK];       // per-block sums
__device__ int g_row[NN + 1];
__device__ int g_cursor[NN];
__device__ int g_csr_src[ET];

// ---------------- helpers ----------------
__device__ __forceinline__ void atomicMaxF(float* addr, float v) {
    if (v >= 0.f) atomicMax((int*)addr, __float_as_int(v));
    else          atomicMin((unsigned int*)addr, __float_as_uint(v));
}

__device__ __forceinline__ unsigned long long pk2(float lo, float hi) {
    unsigned long long r;
    asm("mov.b64 %0, {%1,%2};" : "=l"(r) : "f"(lo), "f"(hi));
    return r;
}
__device__ __forceinline__ void unpk2(unsigned long long v, float& lo, float& hi) {
    asm("mov.b64 {%0,%1}, %2;" : "=f"(lo), "=f"(hi) : "l"(v));
}
__device__ __forceinline__ void fma2(unsigned long long& acc, unsigned long long a,
                                     unsigned long long b) {
    asm("fma.rn.f32x2 %0, %1, %2, %0;" : "+l"(acc) : "l"(a), "l"(b));
}

// ================= CSR build =================
__global__ void k_hist(const int* __restrict__ dst) {
    int e = blockIdx.x * blockDim.x + threadIdx.x;
    if (e >= ET) return;
    int d = (e < EE) ? dst[e] : (e - EE);
    atomicAdd(&g_deg[d], 1);
}

__global__ void k_scan_block() {
    __shared__ int sm[256];
    int t = threadIdx.x;
    int i = blockIdx.x * 256 + t;
    // fold head-state init in here (removes 2 memset graph nodes)
    if (i < GG * HH) g_pool[i] = -CUDART_INF_F;
    if (i < GG) g_root[i] = 0x7FFFFFFF;
    int v = (i < NN) ? g_deg[i] : 0;
    sm[t] = v;
    __syncthreads();
#pragma unroll
    for (int off = 1; off < 256; off <<= 1) {
        int u = (t >= off) ? sm[t - off] : 0;
        __syncthreads();
        sm[t] += u;
        __syncthreads();
    }
    if (i < NN) g_tmp[i] = sm[t] - v;       // exclusive within block
    if (t == 255) g_part[blockIdx.x] = sm[255];
}

// fused: per-block prefix of g_part + final add
__global__ void k_scan_add() {
    __shared__ int s_sum;
    int t = threadIdx.x, bid = blockIdx.x;
    if (t == 0) s_sum = 0;
    __syncthreads();
    int v = 0;
    for (int j = t; j < bid; j += 256) v += g_part[j];
#pragma unroll
    for (int o = 16; o; o >>= 1) v += __shfl_xor_sync(0xFFFFFFFFu, v, o);
    if ((t & 31) == 0 && v) atomicAdd(&s_sum, v);
    __syncthreads();
    int i = bid * 256 + t;
    if (i < NN) {
        int r = g_tmp[i] + s_sum;
        g_row[i] = r;
        g_cursor[i] = r;
    }
    if (i == 0) g_row[NN] = ET;
}

__global__ void k_scatter(const int* __restrict__ src, const int* __restrict__ dst) {
    int e = blockIdx.x * blockDim.x + threadIdx.x;
    if (e >= ET) return;
    int s, d;
    if (e < EE) { s = src[e]; d = dst[e]; } else { s = d = e - EE; }
    int pos = atomicAdd(&g_cursor[d], 1);
    g_csr_src[pos] = s;
}

// ================= GEMM + fused alpha epilogue =================
// C[N,64] = A[N,DIN] @ W[DIN,64]; also as/ad = C . a_src / a_dst per row.
// 256x64 tile, BK=16, 256 threads, 8x8 micro-tile, double-buffered smem with
// register prefetch: LDG(it+1) -> compute(it) -> STS(it+1) -> one sync per tile.
template <int DIN>
__global__ void __launch_bounds__(256) k_gemm(
        const float* __restrict__ A, const float* __restrict__ W,
        const float* __restrict__ asrc, const float* __restrict__ adst) {
    __shared__ float As[2][16][256];    // [buf][k][row]
    __shared__ float Bs[2][16][64];

    const float* Ap = A ? A : g_act;
    int tid = threadIdx.x;
    int rg = tid >> 3;               // 0..31 row group
    int cg = tid & 7;                // 0..7 col group
    int row0 = blockIdx.x * 256;

    int bk = tid >> 4, bq = tid & 15;   // B loader

    unsigned long long acc[8][4] = {};  // 8 rows x 8 cols (4 f32x2)

    int arow = row0 + tid;
    const float* aptr = (arow < NN) ? (Ap + (size_t)arow * DIN) : nullptr;
    const float* bptr = W + (size_t)bk * 64 + bq * 4;

    constexpr int NIT = DIN / 16;
    float4 pa[4], pb;

    // prologue: load tile 0
#pragma unroll
    for (int q = 0; q < 4; q++) {
        pa[q] = make_float4(0.f, 0.f, 0.f, 0.f);
        if (aptr) pa[q] = *(const float4*)(aptr + q * 4);
    }
    pb = *(const float4*)(bptr);
#pragma unroll
    for (int q = 0; q < 4; q++) {
        As[0][q * 4 + 0][tid] = pa[q].x;
        As[0][q * 4 + 1][tid] = pa[q].y;
        As[0][q * 4 + 2][tid] = pa[q].z;
        As[0][q * 4 + 3][tid] = pa[q].w;
    }
    *(float4*)(&Bs[0][bk][bq * 4]) = pb;
    __syncthreads();

    for (int it = 0; it < NIT; ++it) {
        int cur = it & 1;
        // prefetch next tile into registers (overlaps with compute below)
        if (it + 1 < NIT) {
            int k0 = (it + 1) * 16;
#pragma unroll
            for (int q = 0; q < 4; q++) {
                pa[q] = make_float4(0.f, 0.f, 0.f, 0.f);
                if (aptr) pa[q] = *(const float4*)(aptr + k0 + q * 4);
            }
            pb = *(const float4*)(bptr + (size_t)k0 * 64);
        }

#pragma unroll
        for (int k = 0; k < 16; k++) {
            float4 alo = *(float4*)(&As[cur][k][rg * 8]);
            float4 ahi = *(float4*)(&As[cur][k][rg * 8 + 4]);
            float4 blo = *(float4*)(&Bs[cur][k][cg * 4]);
            float4 bhi = *(float4*)(&Bs[cur][k][32 + cg * 4]);
            unsigned long long b0 = pk2(blo.x, blo.y);
            unsigned long long b1 = pk2(blo.z, blo.w);
            unsigned long long b2 = pk2(bhi.x, bhi.y);
            unsigned long long b3 = pk2(bhi.z, bhi.w);
            float a[8] = {alo.x, alo.y, alo.z, alo.w, ahi.x, ahi.y, ahi.z, ahi.w};
#pragma unroll
            for (int r = 0; r < 8; r++) {
                unsigned long long ad = pk2(a[r], a[r]);
                fma2(acc[r][0], ad, b0);
                fma2(acc[r][1], ad, b1);
                fma2(acc[r][2], ad, b2);
                fma2(acc[r][3], ad, b3);
            }
        }

        if (it + 1 < NIT) {
            int nxt = cur ^ 1;
#pragma unroll
            for (int q = 0; q < 4; q++) {
                As[nxt][q * 4 + 0][tid] = pa[q].x;
                As[nxt][q * 4 + 1][tid] = pa[q].y;
                As[nxt][q * 4 + 2][tid] = pa[q].z;
                As[nxt][q * 4 + 3][tid] = pa[q].w;
            }
            *(float4*)(&Bs[nxt][bk][bq * 4]) = pb;
        }
        __syncthreads();
    }

    // epilogue: store h (cols cg*4..+4 and 32+cg*4..+4), reduce alpha over 8-lane seg
    float4 aslo = *(const float4*)(asrc + cg * 4);
    float4 ashi = *(const float4*)(asrc + 32 + cg * 4);
    float4 adlo = *(const float4*)(adst + cg * 4);
    float4 adhi = *(const float4*)(adst + 32 + cg * 4);
    int lane = tid & 31;
    unsigned seg_mask = 0xFFu << (lane & 24);

#pragma unroll
    for (int i = 0; i < 8; i++) {
        int r = row0 + rg * 8 + i;
        float4 vlo, vhi;
        unpk2(acc[i][0], vlo.x, vlo.y);
        unpk2(acc[i][1], vlo.z, vlo.w);
        unpk2(acc[i][2], vhi.x, vhi.y);
        unpk2(acc[i][3], vhi.z, vhi.w);
        if (r < NN) {
            float* hp = g_h + (size_t)r * 64;
            *(float4*)(hp + cg * 4)      = vlo;
            *(float4*)(hp + 32 + cg * 4) = vhi;
        }
        float s = vlo.x * aslo.x + vlo.y * aslo.y + vlo.z * aslo.z + vlo.w * aslo.w
                + vhi.x * ashi.x + vhi.y * ashi.y + vhi.z * ashi.z + vhi.w * ashi.w;
        float d = vlo.x * adlo.x + vlo.y * adlo.y + vlo.z * adlo.z + vlo.w * adlo.w
                + vhi.x * adhi.x + vhi.y * adhi.y + vhi.z * adhi.z + vhi.w * adhi.w;
#pragma unroll
        for (int o = 4; o; o >>= 1) {
            s += __shfl_xor_sync(seg_mask, s, o, 8);
            d += __shfl_xor_sync(seg_mask, d, o, 8);
        }
        if (cg == 0 && r < NN) { g_as[r] = s; g_ad[r] = d; }
    }
}

// ================= fused GAT aggregation: 16 lanes per dst node =================
__global__ void k_gat_agg(const float* __restrict__ b) {
    int t = blockIdx.x * blockDim.x + threadIdx.x;
    int node = t >> 4;
    int ln = threadIdx.x & 15;
    if (node >= NN) return;
    unsigned seg_mask = 0xFFFFu << (threadIdx.x & 16);

    int row = g_row[node], end = g_row[node + 1];
    int deg = end - row;
    float ad = g_ad[node];

    // scores + segment max (cache per-lane score/src for deg<=16)
    float m = -CUDART_INF_F;
    float myv = 0.f; int mys = 0;
    for (int i = row + ln; i < end; i += 16) {
        int s = g_csr_src[i];
        float v = g_as[s] + ad;
        v = fmaxf(v, 0.2f * v);          // leaky_relu(0.2)
        mys = s; myv = v;
        m = fmaxf(m, v);
    }
#pragma unroll
    for (int o = 8; o; o >>= 1) m = fmaxf(m, __shfl_xor_sync(seg_mask, m, o, 16));

    float den = 0.f;
    unsigned long long acc01 = 0, acc23 = 0;   // this lane's float4 of the output row

    if (deg <= 16) {
        float num = 0.f; int s = 0;
        if (ln < deg) { num = __expf(myv - m); s = mys; }
        den = num;
#pragma unroll 4
        for (int j = 0; j < deg; j++) {
            float c = __shfl_sync(seg_mask, num, j, 16);
            int  ss = __shfl_sync(seg_mask, s, j, 16);
            float4 hv = *((const float4*)(g_h + (size_t)ss * 64) + ln);
            unsigned long long cc = pk2(c, c);
            fma2(acc01, pk2(hv.x, hv.y), cc);
            fma2(acc23, pk2(hv.z, hv.w), cc);
        }
    } else {
        for (int base = row; base < end; base += 16) {
            int i = base + ln;
            int s = 0; float num = 0.f;
            if (i < end) {
                s = g_csr_src[i];
                float v = g_as[s] + ad;
                v = fmaxf(v, 0.2f * v);
                num = __expf(v - m);
            }
            den += num;
            int cnt = min(16, end - base);
            for (int j = 0; j < cnt; j++) {
                float c = __shfl_sync(seg_mask, num, j, 16);
                int  ss = __shfl_sync(seg_mask, s, j, 16);
                float4 hv = *((const float4*)(g_h + (size_t)ss * 64) + ln);
                unsigned long long cc = pk2(c, c);
                fma2(acc01, pk2(hv.x, hv.y), cc);
                fma2(acc23, pk2(hv.z, hv.w), cc);
            }
        }
    }
#pragma unroll
    for (int o = 8; o; o >>= 1) den += __shfl_xor_sync(seg_mask, den, o, 16);

    float inv = 1.f / (den + 1e-16f);
    float4 a, b4 = ((const float4*)b)[ln];
    unpk2(acc01, a.x, a.y);
    unpk2(acc23, a.z, a.w);
    float4 o4;
    o4.x = fmaxf(a.x * inv + b4.x, 0.f);
    o4.y = fmaxf(a.y * inv + b4.y, 0.f);
    o4.z = fmaxf(a.z * inv + b4.z, 0.f);
    o4.w = fmaxf(a.w * inv + b4.w, 0.f);
    *((float4*)(g_act + (size_t)node * 64) + ln) = o4;
}

// ================= pooling (with fused root detection) / head =================
__global__ void k_pool(const int* __restrict__ batch) {
    int n0 = blockIdx.x * 128;
    int c = threadIdx.x;          // 0..63
    int nend = min(n0 + 128, NN);
    float cur = 0.f; int curg = -1;
    for (int n = n0 + threadIdx.y; n < nend; n += 4) {
        int g = batch[n];
        if (c == 0) {             // root detection: first index of each graph
            if (n == 0 || batch[n - 1] != g) atomicMin(&g_root[g], n);
        }
        float v = g_act[(size_t)n * 64 + c];
        if (g != curg) {
            if (curg >= 0) atomicMaxF(&g_pool[curg * 64 + c], cur);
            curg = g; cur = v;
        } else {
            cur = fmaxf(cur, v);
        }
    }
    if (curg >= 0) atomicMaxF(&g_pool[curg * 64 + c], cur);
}

__global__ void k_head(const float* __restrict__ x,
                       const float* __restrict__ lnW, const float* __restrict__ lnb,
                       const float* __restrict__ l0W, const float* __restrict__ l0b,
                       const float* __restrict__ l1W, const float* __restrict__ l1b,
                       float* __restrict__ out) {
    int g = blockIdx.x;
    int c = threadIdx.x;   // 0..63
    __shared__ float red[2];

    float acc = l0b[c];
#pragma unroll 8
    for (int k = 0; k < 64; k++) acc += g_pool[g * 64 + k] * l0W[k * 64 + c];
    float hp = fmaxf(acc, 0.f);

    const float* xr = x + (size_t)g_root[g] * DIN0;
    float accn = lnb[c];
#pragma unroll 8
    for (int k = 0; k < 128; k++) accn += xr[k] * lnW[k * 64 + c];
    float nw = fmaxf(accn, 0.f);

    float p = hp * l1W[c] + nw * l1W[64 + c];
#pragma unroll
    for (int o = 16; o; o >>= 1) p += __shfl_xor_sync(0xFFFFFFFFu, p, o);
    if ((c & 31) == 0) red[c >> 5] = p;
    __syncthreads();
    if (c == 0) {
        float z = red[0] + red[1] + l1b[0];
        out[g] = 1.f / (1.f + __expf(-z));
    }
}

// ================= launch =================
extern "C" void kernel_launch(void* const* d_in, const int* in_sizes, int n_in,
                              void* d_out, int out_size) {
    const float* x      = (const float*)d_in[0];
    const int*   adj    = (const int*)d_in[1];
    const int*   batch  = (const int*)d_in[2];
    const float* W1     = (const float*)d_in[3];
    const float* asrc1  = (const float*)d_in[4];
    const float* adst1  = (const float*)d_in[5];
    const float* b1     = (const float*)d_in[6];
    const float* W2     = (const float*)d_in[7];
    const float* asrc2  = (const float*)d_in[8];
    const float* adst2  = (const float*)d_in[9];
    const float* b2     = (const float*)d_in[10];
    const float* W3     = (const float*)d_in[11];
    const float* asrc3  = (const float*)d_in[12];
    const float* adst3  = (const float*)d_in[13];
    const float* b3     = (const float*)d_in[14];
    const float* lnW    = (const float*)d_in[15];
    const float* lnb    = (const float*)d_in[16];
    const float* l0W    = (const float*)d_in[17];
    const float* l0b    = (const float*)d_in[18];
    const float* l1W    = (const float*)d_in[19];
    const float* l1b    = (const float*)d_in[20];
    float* out = (float*)d_out;

    const int* src = adj;
    const int* dst = adj + EE;

    void* p_deg = nullptr;
    cudaGetSymbolAddress(&p_deg, g_deg);

    const int GEMM_GRID  = (NN + 255) / 256;          // 391
    const int EDGE_GRID  = (ET + 255) / 256;          // 4297
    const int AGG_GRID   = (NN * 16 + 255) / 256;     // 6250 (16 lanes per node)

    // ---- CSR build (launch order keeps gemm1 at kernel #4 for profiling) ----
    cudaMemsetAsync(p_deg, 0, NN * sizeof(int));
    k_hist<<<EDGE_GRID, 256>>>(dst);                          // 1
    k_scan_block<<<NBLK, 256>>>();                            // 2 (also inits pool/root)
    k_scan_add<<<NBLK, 256>>>();                              // 3
    k_gemm<128><<<GEMM_GRID, 256>>>(x, W1, asrc1, adst1);     // 4 <- profiled
    k_scatter<<<EDGE_GRID, 256>>>(src, dst);                  // 5
    k_gat_agg<<<AGG_GRID, 256>>>(b1);                         // 6

    // ---- layer 2 / 3 ----
    k_gemm<64><<<GEMM_GRID, 256>>>(nullptr, W2, asrc2, adst2);
    k_gat_agg<<<AGG_GRID, 256>>>(b2);
    k_gemm<64><<<GEMM_GRID, 256>>>(nullptr, W3, asrc3, adst3);
    k_gat_agg<<<AGG_GRID, 256>>>(b3);

    // ---- head ----
    k_pool<<<(NN + 127) / 128, dim3(64, 4)>>>(batch);
    k_head<<<GG, 64>>>(x, lnW, lnb, l0W, l0b, l1W, l1b, out);
}

// round 13
// speedup vs baseline: 1.7611x; 1.0275x over previous
#include <cuda_runtime.h>
#include <cuda_bf16.h>
#include <math_constants.h>

// Problem constants
#define NN 100000
#define EE 1000000
#define ET (NN + EE)        // edges incl. self-loops = 1,100,000
#define GG 64
#define HH 64
#define DIN0 128
#define NBLK ((NN + 255) / 256)   // 391

// ---------------- device scratch (no allocations allowed) ----------------
__device__ float g_h[(size_t)NN * HH];      // h = x @ W (pre-bias)
__device__ float g_act[(size_t)NN * HH];    // relu(agg + b) -> next layer input
__device__ float g_as[NN];                  // h . a_src per node
__device__ float g_ad[NN];                  // h . a_dst per node
__device__ float g_pool[GG * HH];
__device__ int   g_root[GG];

// CSR by dst (rebuilt every call; graph static across layers)
__device__ int g_deg[NN];
__device__ int g_tmp[NN];          // block-local exclusive scan
__device__ int g_part[NBLK];       // per-block sums
__device__ int g_row[NN + 1];
__device__ int g_cursor[NN];
__device__ int g_csr_src[ET];

// ---------------- helpers ----------------
__device__ __forceinline__ void atomicMaxF(float* addr, float v) {
    if (v >= 0.f) atomicMax((int*)addr, __float_as_int(v));
    else          atomicMin((unsigned int*)addr, __float_as_uint(v));
}

__device__ __forceinline__ unsigned long long pk2(float lo, float hi) {
    unsigned long long r;
    asm("mov.b64 %0, {%1,%2};" : "=l"(r) : "f"(lo), "f"(hi));
    return r;
}
__device__ __forceinline__ void unpk2(unsigned long long v, float& lo, float& hi) {
    asm("mov.b64 {%0,%1}, %2;" : "=f"(lo), "=f"(hi) : "l"(v));
}
__device__ __forceinline__ void fma2(unsigned long long& acc, unsigned long long a,
                                     unsigned long long b) {
    asm("fma.rn.f32x2 %0, %1, %2, %0;" : "+l"(acc) : "l"(a), "l"(b));
}

// ================= CSR build =================
__global__ void k_hist(const int* __restrict__ dst) {
    int e = blockIdx.x * blockDim.x + threadIdx.x;
    if (e >= ET) return;
    int d = (e < EE) ? dst[e] : (e - EE);
    atomicAdd(&g_deg[d], 1);
}

__global__ void k_scan_block() {
    __shared__ int sm[256];
    int t = threadIdx.x;
    int i = blockIdx.x * 256 + t;
    // fold head-state init in here
    if (i < GG * HH) g_pool[i] = -CUDART_INF_F;
    if (i < GG) g_root[i] = 0x7FFFFFFF;
    int v = (i < NN) ? g_deg[i] : 0;
    sm[t] = v;
    __syncthreads();
#pragma unroll
    for (int off = 1; off < 256; off <<= 1) {
        int u = (t >= off) ? sm[t - off] : 0;
        __syncthreads();
        sm[t] += u;
        __syncthreads();
    }
    if (i < NN) g_tmp[i] = sm[t] - v;       // exclusive within block
    if (t == 255) g_part[blockIdx.x] = sm[255];
}

// fused: per-block prefix of g_part + final add
__global__ void k_scan_add() {
    __shared__ int s_sum;
    int t = threadIdx.x, bid = blockIdx.x;
    if (t == 0) s_sum = 0;
    __syncthreads();
    int v = 0;
    for (int j = t; j < bid; j += 256) v += g_part[j];
#pragma unroll
    for (int o = 16; o; o >>= 1) v += __shfl_xor_sync(0xFFFFFFFFu, v, o);
    if ((t & 31) == 0 && v) atomicAdd(&s_sum, v);
    __syncthreads();
    int i = bid * 256 + t;
    if (i < NN) {
        int r = g_tmp[i] + s_sum;
        g_row[i] = r;
        g_cursor[i] = r;
    }
    if (i == 0) g_row[NN] = ET;
}

__global__ void k_scatter(const int* __restrict__ src, const int* __restrict__ dst) {
    int e = blockIdx.x * blockDim.x + threadIdx.x;
    if (e >= ET) return;
    int s, d;
    if (e < EE) { s = src[e]; d = dst[e]; } else { s = d = e - EE; }
    int pos = atomicAdd(&g_cursor[d], 1);
    g_csr_src[pos] = s;
}

// ================= GEMM + fused alpha epilogue =================
// C[N,64] = A[N,DIN] @ W[DIN,64]; also as/ad = C . a_src / a_dst per row.
// 128x64 tile, BK=16, 256 threads, 4x8 micro-tile (32-reg accumulator for
// 3 CTAs/SM), double-buffered smem + register prefetch. A stored with padded
// groups: row-group g (4 floats) at slot g*8 -> warp's 4 groups on distinct
// bank quads {0-3}/{8-11}/{16-19}/{24-27}: conflict-free LDS.128.
template <int DIN>
__global__ void __launch_bounds__(256, 3) k_gemm(
        const float* __restrict__ A, const float* __restrict__ W,
        const float* __restrict__ asrc, const float* __restrict__ adst) {
    __shared__ float As[2][16][256];    // [buf][k][padded slot]: 32 groups * 8
    __shared__ float Bs[2][16][64];

    const float* Ap = A ? A : g_act;
    int tid = threadIdx.x;
    int rg = tid >> 3;               // 0..31 row group (4 rows each)
    int cg = tid & 7;                // 0..7 col group
    int row0 = blockIdx.x * 128;

    // A loader: thread covers row lrow, k-half lk (8 floats)
    int lrow = tid >> 1;
    int lk   = (tid & 1) * 8;
    int slot = (lrow >> 2) * 8 + (lrow & 3);
    // B loader
    int bk = tid >> 4, bq = tid & 15;

    unsigned long long acc[4][4] = {};  // 4 rows x 8 cols (4 f32x2)

    int arow = row0 + lrow;
    const float* aptr = (arow < NN) ? (Ap + (size_t)arow * DIN + lk) : nullptr;
    const float* bptr = W + (size_t)bk * 64 + bq * 4;

    constexpr int NIT = DIN / 16;
    float4 pa0, pa1, pb;

    // prologue: load tile 0
    pa0 = make_float4(0.f, 0.f, 0.f, 0.f);
    pa1 = pa0;
    if (aptr) { pa0 = *(const float4*)(aptr); pa1 = *(const float4*)(aptr + 4); }
    pb = *(const float4*)(bptr);
    {
        As[0][lk + 0][slot] = pa0.x;  As[0][lk + 1][slot] = pa0.y;
        As[0][lk + 2][slot] = pa0.z;  As[0][lk + 3][slot] = pa0.w;
        As[0][lk + 4][slot] = pa1.x;  As[0][lk + 5][slot] = pa1.y;
        As[0][lk + 6][slot] = pa1.z;  As[0][lk + 7][slot] = pa1.w;
        *(float4*)(&Bs[0][bk][bq * 4]) = pb;
    }
    __syncthreads();

    for (int it = 0; it < NIT; ++it) {
        int cur = it & 1;
        if (it + 1 < NIT) {
            int k0 = (it + 1) * 16;
            pa0 = make_float4(0.f, 0.f, 0.f, 0.f);
            pa1 = pa0;
            if (aptr) { pa0 = *(const float4*)(aptr + k0); pa1 = *(const float4*)(aptr + k0 + 4); }
            pb = *(const float4*)(bptr + (size_t)k0 * 64);
        }

#pragma unroll
        for (int k = 0; k < 16; k++) {
            float4 av  = *(float4*)(&As[cur][k][rg * 8]);       // rows rg*4..+3
            float4 blo = *(float4*)(&Bs[cur][k][cg * 4]);
            float4 bhi = *(float4*)(&Bs[cur][k][32 + cg * 4]);
            unsigned long long b0 = pk2(blo.x, blo.y);
            unsigned long long b1 = pk2(blo.z, blo.w);
            unsigned long long b2 = pk2(bhi.x, bhi.y);
            unsigned long long b3 = pk2(bhi.z, bhi.w);
            float a[4] = {av.x, av.y, av.z, av.w};
#pragma unroll
            for (int r = 0; r < 4; r++) {
                unsigned long long ad = pk2(a[r], a[r]);
                fma2(acc[r][0], ad, b0);
                fma2(acc[r][1], ad, b1);
                fma2(acc[r][2], ad, b2);
                fma2(acc[r][3], ad, b3);
            }
        }

        if (it + 1 < NIT) {
            int nxt = cur ^ 1;
            As[nxt][lk + 0][slot] = pa0.x;  As[nxt][lk + 1][slot] = pa0.y;
            As[nxt][lk + 2][slot] = pa0.z;  As[nxt][lk + 3][slot] = pa0.w;
            As[nxt][lk + 4][slot] = pa1.x;  As[nxt][lk + 5][slot] = pa1.y;
            As[nxt][lk + 6][slot] = pa1.z;  As[nxt][lk + 7][slot] = pa1.w;
            *(float4*)(&Bs[nxt][bk][bq * 4]) = pb;
        }
        __syncthreads();
    }

    // epilogue: store h (cols cg*4..+4 and 32+cg*4..+4), reduce alpha over 8-lane seg
    float4 aslo = *(const float4*)(asrc + cg * 4);
    float4 ashi = *(const float4*)(asrc + 32 + cg * 4);
    float4 adlo = *(const float4*)(adst + cg * 4);
    float4 adhi = *(const float4*)(adst + 32 + cg * 4);
    int lane = tid & 31;
    unsigned seg_mask = 0xFFu << (lane & 24);

#pragma unroll
    for (int i = 0; i < 4; i++) {
        int r = row0 + rg * 4 + i;
        float4 vlo, vhi;
        unpk2(acc[i][0], vlo.x, vlo.y);
        unpk2(acc[i][1], vlo.z, vlo.w);
        unpk2(acc[i][2], vhi.x, vhi.y);
        unpk2(acc[i][3], vhi.z, vhi.w);
        if (r < NN) {
            float* hp = g_h + (size_t)r * 64;
            *(float4*)(hp + cg * 4)      = vlo;
            *(float4*)(hp + 32 + cg * 4) = vhi;
        }
        float s = vlo.x * aslo.x + vlo.y * aslo.y + vlo.z * aslo.z + vlo.w * aslo.w
                + vhi.x * ashi.x + vhi.y * ashi.y + vhi.z * ashi.z + vhi.w * ashi.w;
        float d = vlo.x * adlo.x + vlo.y * adlo.y + vlo.z * adlo.z + vlo.w * adlo.w
                + vhi.x * adhi.x + vhi.y * adhi.y + vhi.z * adhi.z + vhi.w * adhi.w;
#pragma unroll
        for (int o = 4; o; o >>= 1) {
            s += __shfl_xor_sync(seg_mask, s, o, 8);
            d += __shfl_xor_sync(seg_mask, d, o, 8);
        }
        if (cg == 0 && r < NN) { g_as[r] = s; g_ad[r] = d; }
    }
}

// ================= fused GAT aggregation: 16 lanes per dst node =================
__global__ void k_gat_agg(const float* __restrict__ b) {
    int t = blockIdx.x * blockDim.x + threadIdx.x;
    int node = t >> 4;
    int ln = threadIdx.x & 15;
    if (node >= NN) return;
    unsigned seg_mask = 0xFFFFu << (threadIdx.x & 16);

    int row = g_row[node], end = g_row[node + 1];
    int deg = end - row;
    float ad = g_ad[node];

    // scores + segment max (cache per-lane score/src for deg<=16)
    float m = -CUDART_INF_F;
    float myv = 0.f; int mys = 0;
    for (int i = row + ln; i < end; i += 16) {
        int s = g_csr_src[i];
        float v = g_as[s] + ad;
        v = fmaxf(v, 0.2f * v);          // leaky_relu(0.2)
        mys = s; myv = v;
        m = fmaxf(m, v);
    }
#pragma unroll
    for (int o = 8; o; o >>= 1) m = fmaxf(m, __shfl_xor_sync(seg_mask, m, o, 16));

    float den = 0.f;
    unsigned long long acc01 = 0, acc23 = 0;   // this lane's float4 of the output row

    if (deg <= 16) {
        float num = 0.f; int s = 0;
        if (ln < deg) { num = __expf(myv - m); s = mys; }
        den = num;
#pragma unroll 4
        for (int j = 0; j < deg; j++) {
            float c = __shfl_sync(seg_mask, num, j, 16);
            int  ss = __shfl_sync(seg_mask, s, j, 16);
            float4 hv = *((const float4*)(g_h + (size_t)ss * 64) + ln);
            unsigned long long cc = pk2(c, c);
            fma2(acc01, pk2(hv.x, hv.y), cc);
            fma2(acc23, pk2(hv.z, hv.w), cc);
        }
    } else {
        for (int base = row; base < end; base += 16) {
            int i = base + ln;
            int s = 0; float num = 0.f;
            if (i < end) {
                s = g_csr_src[i];
                float v = g_as[s] + ad;
                v = fmaxf(v, 0.2f * v);
                num = __expf(v - m);
            }
            den += num;
            int cnt = min(16, end - base);
            for (int j = 0; j < cnt; j++) {
                float c = __shfl_sync(seg_mask, num, j, 16);
                int  ss = __shfl_sync(seg_mask, s, j, 16);
                float4 hv = *((const float4*)(g_h + (size_t)ss * 64) + ln);
                unsigned long long cc = pk2(c, c);
                fma2(acc01, pk2(hv.x, hv.y), cc);
                fma2(acc23, pk2(hv.z, hv.w), cc);
            }
        }
    }
#pragma unroll
    for (int o = 8; o; o >>= 1) den += __shfl_xor_sync(seg_mask, den, o, 16);

    float inv = 1.f / (den + 1e-16f);
    float4 a, b4 = ((const float4*)b)[ln];
    unpk2(acc01, a.x, a.y);
    unpk2(acc23, a.z, a.w);
    float4 o4;
    o4.x = fmaxf(a.x * inv + b4.x, 0.f);
    o4.y = fmaxf(a.y * inv + b4.y, 0.f);
    o4.z = fmaxf(a.z * inv + b4.z, 0.f);
    o4.w = fmaxf(a.w * inv + b4.w, 0.f);
    *((float4*)(g_act + (size_t)node * 64) + ln) = o4;
}

// ================= pooling (with fused root detection) / head =================
__global__ void k_pool(const int* __restrict__ batch) {
    int n0 = blockIdx.x * 128;
    int c = threadIdx.x;          // 0..63
    int nend = min(n0 + 128, NN);
    float cur = 0.f; int curg = -1;
    for (int n = n0 + threadIdx.y; n < nend; n += 4) {
        int g = batch[n];
        if (c == 0) {             // root detection: first index of each graph
            if (n == 0 || batch[n - 1] != g) atomicMin(&g_root[g], n);
        }
        float v = g_act[(size_t)n * 64 + c];
        if (g != curg) {
            if (curg >= 0) atomicMaxF(&g_pool[curg * 64 + c], cur);
            curg = g; cur = v;
        } else {
            cur = fmaxf(cur, v);
        }
    }
    if (curg >= 0) atomicMaxF(&g_pool[curg * 64 + c], cur);
}

__global__ void k_head(const float* __restrict__ x,
                       const float* __restrict__ lnW, const float* __restrict__ lnb,
                       const float* __restrict__ l0W, const float* __restrict__ l0b,
                       const float* __restrict__ l1W, const float* __restrict__ l1b,
                       float* __restrict__ out) {
    int g = blockIdx.x;
    int c = threadIdx.x;   // 0..63
    __shared__ float red[2];

    float acc = l0b[c];
#pragma unroll 8
    for (int k = 0; k < 64; k++) acc += g_pool[g * 64 + k] * l0W[k * 64 + c];
    float hp = fmaxf(acc, 0.f);

    const float* xr = x + (size_t)g_root[g] * DIN0;
    float accn = lnb[c];
#pragma unroll 8
    for (int k = 0; k < 128; k++) accn += xr[k] * lnW[k * 64 + c];
    float nw = fmaxf(accn, 0.f);

    float p = hp * l1W[c] + nw * l1W[64 + c];
#pragma unroll
    for (int o = 16; o; o >>= 1) p += __shfl_xor_sync(0xFFFFFFFFu, p, o);
    if ((c & 31) == 0) red[c >> 5] = p;
    __syncthreads();
    if (c == 0) {
        float z = red[0] + red[1] + l1b[0];
        out[g] = 1.f / (1.f + __expf(-z));
    }
}

// ================= launch =================
extern "C" void kernel_launch(void* const* d_in, const int* in_sizes, int n_in,
                              void* d_out, int out_size) {
    const float* x      = (const float*)d_in[0];
    const int*   adj    = (const int*)d_in[1];
    const int*   batch  = (const int*)d_in[2];
    const float* W1     = (const float*)d_in[3];
    const float* asrc1  = (const float*)d_in[4];
    const float* adst1  = (const float*)d_in[5];
    const float* b1     = (const float*)d_in[6];
    const float* W2     = (const float*)d_in[7];
    const float* asrc2  = (const float*)d_in[8];
    const float* adst2  = (const float*)d_in[9];
    const float* b2     = (const float*)d_in[10];
    const float* W3     = (const float*)d_in[11];
    const float* asrc3  = (const float*)d_in[12];
    const float* adst3  = (const float*)d_in[13];
    const float* b3     = (const float*)d_in[14];
    const float* lnW    = (const float*)d_in[15];
    const float* lnb    = (const float*)d_in[16];
    const float* l0W    = (const float*)d_in[17];
    const float* l0b    = (const float*)d_in[18];
    const float* l1W    = (const float*)d_in[19];
    const float* l1b    = (const float*)d_in[20];
    float* out = (float*)d_out;

    const int* src = adj;
    const int* dst = adj + EE;

    void* p_deg = nullptr;
    cudaGetSymbolAddress(&p_deg, g_deg);

    const int GEMM_GRID  = (NN + 127) / 128;          // 782
    const int EDGE_GRID  = (ET + 255) / 256;          // 4297
    const int AGG_GRID   = (NN * 16 + 255) / 256;     // 6250 (16 lanes per node)

    // ---- CSR build (launch order keeps gemm1 at kernel #4 for profiling) ----
    cudaMemsetAsync(p_deg, 0, NN * sizeof(int));
    k_hist<<<EDGE_GRID, 256>>>(dst);                          // 1
    k_scan_block<<<NBLK, 256>>>();                            // 2 (also inits pool/root)
    k_scan_add<<<NBLK, 256>>>();                              // 3
    k_gemm<128><<<GEMM_GRID, 256>>>(x, W1, asrc1, adst1);     // 4 <- profiled
    k_scatter<<<EDGE_GRID, 256>>>(src, dst);                  // 5
    k_gat_agg<<<AGG_GRID, 256>>>(b1);                         // 6

    // ---- layer 2 / 3 ----
    k_gemm<64><<<GEMM_GRID, 256>>>(nullptr, W2, asrc2, adst2);
    k_gat_agg<<<AGG_GRID, 256>>>(b2);
    k_gemm<64><<<GEMM_GRID, 256>>>(nullptr, W3, asrc3, adst3);
    k_gat_agg<<<AGG_GRID, 256>>>(b3);

    // ---- head ----
    k_pool<<<(NN + 127) / 128, dim3(64, 4)>>>(batch);
    k_head<<<GG, 64>>>(x, lnW, lnb, l0W, l0b, l1W, l1b, out);
}

// round 14
// speedup vs baseline: 1.7727x; 1.0066x over previous
#include <cuda_runtime.h>
#include <cuda_bf16.h>
#include <math_constants.h>

// Problem constants
#define NN 100000
#define EE 1000000
#define ET (NN + EE)        // edges incl. self-loops = 1,100,000
#define GG 64
#define HH 64
#define DIN0 128
#define NBLK ((NN + 255) / 256)   // 391

// ---------------- device scratch (no allocations allowed) ----------------
__device__ float g_h[(size_t)NN * HH];      // h = x @ W (pre-bias)
__device__ float g_act[(size_t)NN * HH];    // relu(agg + b) -> next layer input
__device__ float g_as[NN];                  // h . a_src per node
__device__ float g_ad[NN];                  // h . a_dst per node
__device__ float g_pool[GG * HH];
__device__ int   g_root[GG];

// CSR by dst (rebuilt every call; graph static across layers)
__device__ int g_deg[NN];
__device__ int g_tmp[NN];          // block-local exclusive scan
__device__ int g_part[NBLK];       // per-block sums
__device__ int g_row[NN + 1];
__device__ int g_cursor[NN];
__device__ int g_csr_src[ET];

// ---------------- helpers ----------------
__device__ __forceinline__ void atomicMaxF(float* addr, float v) {
    if (v >= 0.f) atomicMax((int*)addr, __float_as_int(v));
    else          atomicMin((unsigned int*)addr, __float_as_uint(v));
}

__device__ __forceinline__ unsigned long long pk2(float lo, float hi) {
    unsigned long long r;
    asm("mov.b64 %0, {%1,%2};" : "=l"(r) : "f"(lo), "f"(hi));
    return r;
}
__device__ __forceinline__ void unpk2(unsigned long long v, float& lo, float& hi) {
    asm("mov.b64 {%0,%1}, %2;" : "=f"(lo), "=f"(hi) : "l"(v));
}
__device__ __forceinline__ void fma2(unsigned long long& acc, unsigned long long a,
                                     unsigned long long b) {
    asm("fma.rn.f32x2 %0, %1, %2, %0;" : "+l"(acc) : "l"(a), "l"(b));
}

// ================= CSR build =================
__global__ void k_hist(const int* __restrict__ dst) {
    int e = blockIdx.x * blockDim.x + threadIdx.x;
    if (e >= ET) return;
    int d = (e < EE) ? dst[e] : (e - EE);
    atomicAdd(&g_deg[d], 1);
}

__global__ void k_scan_block() {
    __shared__ int sm[256];
    int t = threadIdx.x;
    int i = blockIdx.x * 256 + t;
    // fold head-state init in here
    if (i < GG * HH) g_pool[i] = -CUDART_INF_F;
    if (i < GG) g_root[i] = 0x7FFFFFFF;
    int v = (i < NN) ? g_deg[i] : 0;
    sm[t] = v;
    __syncthreads();
#pragma unroll
    for (int off = 1; off < 256; off <<= 1) {
        int u = (t >= off) ? sm[t - off] : 0;
        __syncthreads();
        sm[t] += u;
        __syncthreads();
    }
    if (i < NN) g_tmp[i] = sm[t] - v;       // exclusive within block
    if (t == 255) g_part[blockIdx.x] = sm[255];
}

// fused: per-block prefix of g_part + final add
__global__ void k_scan_add() {
    __shared__ int s_sum;
    int t = threadIdx.x, bid = blockIdx.x;
    if (t == 0) s_sum = 0;
    __syncthreads();
    int v = 0;
    for (int j = t; j < bid; j += 256) v += g_part[j];
#pragma unroll
    for (int o = 16; o; o >>= 1) v += __shfl_xor_sync(0xFFFFFFFFu, v, o);
    if ((t & 31) == 0 && v) atomicAdd(&s_sum, v);
    __syncthreads();
    int i = bid * 256 + t;
    if (i < NN) {
        int r = g_tmp[i] + s_sum;
        g_row[i] = r;
        g_cursor[i] = r;
    }
    if (i == 0) g_row[NN] = ET;
}

__global__ void k_scatter(const int* __restrict__ src, const int* __restrict__ dst) {
    int e = blockIdx.x * blockDim.x + threadIdx.x;
    if (e >= ET) return;
    int s, d;
    if (e < EE) { s = src[e]; d = dst[e]; } else { s = d = e - EE; }
    int pos = atomicAdd(&g_cursor[d], 1);
    g_csr_src[pos] = s;
}

// ================= GEMM + fused alpha epilogue =================
// (unchanged from R13 — 128x64 tile, 4x8 micro-tile, 3 CTAs/SM, double-buffered)
template <int DIN>
__global__ void __launch_bounds__(256, 3) k_gemm(
        const float* __restrict__ A, const float* __restrict__ W,
        const float* __restrict__ asrc, const float* __restrict__ adst) {
    __shared__ float As[2][16][256];    // [buf][k][padded slot]: 32 groups * 8
    __shared__ float Bs[2][16][64];

    const float* Ap = A ? A : g_act;
    int tid = threadIdx.x;
    int rg = tid >> 3;               // 0..31 row group (4 rows each)
    int cg = tid & 7;                // 0..7 col group
    int row0 = blockIdx.x * 128;

    int lrow = tid >> 1;
    int lk   = (tid & 1) * 8;
    int slot = (lrow >> 2) * 8 + (lrow & 3);
    int bk = tid >> 4, bq = tid & 15;

    unsigned long long acc[4][4] = {};  // 4 rows x 8 cols (4 f32x2)

    int arow = row0 + lrow;
    const float* aptr = (arow < NN) ? (Ap + (size_t)arow * DIN + lk) : nullptr;
    const float* bptr = W + (size_t)bk * 64 + bq * 4;

    constexpr int NIT = DIN / 16;
    float4 pa0, pa1, pb;

    pa0 = make_float4(0.f, 0.f, 0.f, 0.f);
    pa1 = pa0;
    if (aptr) { pa0 = *(const float4*)(aptr); pa1 = *(const float4*)(aptr + 4); }
    pb = *(const float4*)(bptr);
    {
        As[0][lk + 0][slot] = pa0.x;  As[0][lk + 1][slot] = pa0.y;
        As[0][lk + 2][slot] = pa0.z;  As[0][lk + 3][slot] = pa0.w;
        As[0][lk + 4][slot] = pa1.x;  As[0][lk + 5][slot] = pa1.y;
        As[0][lk + 6][slot] = pa1.z;  As[0][lk + 7][slot] = pa1.w;
        *(float4*)(&Bs[0][bk][bq * 4]) = pb;
    }
    __syncthreads();

    for (int it = 0; it < NIT; ++it) {
        int cur = it & 1;
        if (it + 1 < NIT) {
            int k0 = (it + 1) * 16;
            pa0 = make_float4(0.f, 0.f, 0.f, 0.f);
            pa1 = pa0;
            if (aptr) { pa0 = *(const float4*)(aptr + k0); pa1 = *(const float4*)(aptr + k0 + 4); }
            pb = *(const float4*)(bptr + (size_t)k0 * 64);
        }

#pragma unroll
        for (int k = 0; k < 16; k++) {
            float4 av  = *(float4*)(&As[cur][k][rg * 8]);
            float4 blo = *(float4*)(&Bs[cur][k][cg * 4]);
            float4 bhi = *(float4*)(&Bs[cur][k][32 + cg * 4]);
            unsigned long long b0 = pk2(blo.x, blo.y);
            unsigned long long b1 = pk2(blo.z, blo.w);
            unsigned long long b2 = pk2(bhi.x, bhi.y);
            unsigned long long b3 = pk2(bhi.z, bhi.w);
            float a[4] = {av.x, av.y, av.z, av.w};
#pragma unroll
            for (int r = 0; r < 4; r++) {
                unsigned long long ad = pk2(a[r], a[r]);
                fma2(acc[r][0], ad, b0);
                fma2(acc[r][1], ad, b1);
                fma2(acc[r][2], ad, b2);
                fma2(acc[r][3], ad, b3);
            }
        }

        if (it + 1 < NIT) {
            int nxt = cur ^ 1;
            As[nxt][lk + 0][slot] = pa0.x;  As[nxt][lk + 1][slot] = pa0.y;
            As[nxt][lk + 2][slot] = pa0.z;  As[nxt][lk + 3][slot] = pa0.w;
            As[nxt][lk + 4][slot] = pa1.x;  As[nxt][lk + 5][slot] = pa1.y;
            As[nxt][lk + 6][slot] = pa1.z;  As[nxt][lk + 7][slot] = pa1.w;
            *(float4*)(&Bs[nxt][bk][bq * 4]) = pb;
        }
        __syncthreads();
    }

    float4 aslo = *(const float4*)(asrc + cg * 4);
    float4 ashi = *(const float4*)(asrc + 32 + cg * 4);
    float4 adlo = *(const float4*)(adst + cg * 4);
    float4 adhi = *(const float4*)(adst + 32 + cg * 4);
    int lane = tid & 31;
    unsigned seg_mask = 0xFFu << (lane & 24);

#pragma unroll
    for (int i = 0; i < 4; i++) {
        int r = row0 + rg * 4 + i;
        float4 vlo, vhi;
        unpk2(acc[i][0], vlo.x, vlo.y);
        unpk2(acc[i][1], vlo.z, vlo.w);
        unpk2(acc[i][2], vhi.x, vhi.y);
        unpk2(acc[i][3], vhi.z, vhi.w);
        if (r < NN) {
            float* hp = g_h + (size_t)r * 64;
            *(float4*)(hp + cg * 4)      = vlo;
            *(float4*)(hp + 32 + cg * 4) = vhi;
        }
        float s = vlo.x * aslo.x + vlo.y * aslo.y + vlo.z * aslo.z + vlo.w * aslo.w
                + vhi.x * ashi.x + vhi.y * ashi.y + vhi.z * ashi.z + vhi.w * ashi.w;
        float d = vlo.x * adlo.x + vlo.y * adlo.y + vlo.z * adlo.z + vlo.w * adlo.w
                + vhi.x * adhi.x + vhi.y * adhi.y + vhi.z * adhi.z + vhi.w * adhi.w;
#pragma unroll
        for (int o = 4; o; o >>= 1) {
            s += __shfl_xor_sync(seg_mask, s, o, 8);
            d += __shfl_xor_sync(seg_mask, d, o, 8);
        }
        if (cg == 0 && r < NN) { g_as[r] = s; g_ad[r] = d; }
    }
}

// ================= fused GAT aggregation: 16 lanes per dst node =================
// x4-unrolled edge loop: 4 independent row-gathers in flight (MLP 4), __ldg path.
__global__ void k_gat_agg(const float* __restrict__ b) {
    int t = blockIdx.x * blockDim.x + threadIdx.x;
    int node = t >> 4;
    int ln = threadIdx.x & 15;
    if (node >= NN) return;
    unsigned seg_mask = 0xFFFFu << (threadIdx.x & 16);

    int row = g_row[node], end = g_row[node + 1];
    int deg = end - row;
    float ad = g_ad[node];

    // scores + segment max (cache per-lane score/src for deg<=16)
    float m = -CUDART_INF_F;
    float myv = 0.f; int mys = 0;
    for (int i = row + ln; i < end; i += 16) {
        int s = __ldg(&g_csr_src[i]);
        float v = __ldg(&g_as[s]) + ad;
        v = fmaxf(v, 0.2f * v);          // leaky_relu(0.2)
        mys = s; myv = v;
        m = fmaxf(m, v);
    }
#pragma unroll
    for (int o = 8; o; o >>= 1) m = fmaxf(m, __shfl_xor_sync(seg_mask, m, o, 16));

    float den = 0.f;
    unsigned long long acc01 = 0, acc23 = 0;   // this lane's float4 of the output row

    if (deg <= 16) {
        float num = 0.f; int s = 0;
        if (ln < deg) { num = __expf(myv - m); s = mys; }
        den = num;
        int j = 0;
        for (; j + 4 <= deg; j += 4) {
            float c0 = __shfl_sync(seg_mask, num, j + 0, 16);
            float c1 = __shfl_sync(seg_mask, num, j + 1, 16);
            float c2 = __shfl_sync(seg_mask, num, j + 2, 16);
            float c3 = __shfl_sync(seg_mask, num, j + 3, 16);
            int  s0 = __shfl_sync(seg_mask, s, j + 0, 16);
            int  s1 = __shfl_sync(seg_mask, s, j + 1, 16);
            int  s2 = __shfl_sync(seg_mask, s, j + 2, 16);
            int  s3 = __shfl_sync(seg_mask, s, j + 3, 16);
            float4 h0 = __ldg((const float4*)(g_h + (size_t)s0 * 64) + ln);
            float4 h1 = __ldg((const float4*)(g_h + (size_t)s1 * 64) + ln);
            float4 h2 = __ldg((const float4*)(g_h + (size_t)s2 * 64) + ln);
            float4 h3 = __ldg((const float4*)(g_h + (size_t)s3 * 64) + ln);
            fma2(acc01, pk2(h0.x, h0.y), pk2(c0, c0));
            fma2(acc23, pk2(h0.z, h0.w), pk2(c0, c0));
            fma2(acc01, pk2(h1.x, h1.y), pk2(c1, c1));
            fma2(acc23, pk2(h1.z, h1.w), pk2(c1, c1));
            fma2(acc01, pk2(h2.x, h2.y), pk2(c2, c2));
            fma2(acc23, pk2(h2.z, h2.w), pk2(c2, c2));
            fma2(acc01, pk2(h3.x, h3.y), pk2(c3, c3));
            fma2(acc23, pk2(h3.z, h3.w), pk2(c3, c3));
        }
        for (; j < deg; j++) {
            float c = __shfl_sync(seg_mask, num, j, 16);
            int  ss = __shfl_sync(seg_mask, s, j, 16);
            float4 hv = __ldg((const float4*)(g_h + (size_t)ss * 64) + ln);
            unsigned long long cc = pk2(c, c);
            fma2(acc01, pk2(hv.x, hv.y), cc);
            fma2(acc23, pk2(hv.z, hv.w), cc);
        }
    } else {
        for (int base = row; base < end; base += 16) {
            int i = base + ln;
            int s = 0; float num = 0.f;
            if (i < end) {
                s = __ldg(&g_csr_src[i]);
                float v = __ldg(&g_as[s]) + ad;
                v = fmaxf(v, 0.2f * v);
                num = __expf(v - m);
            }
            den += num;
            int cnt = min(16, end - base);
            int j = 0;
            for (; j + 4 <= cnt; j += 4) {
                float c0 = __shfl_sync(seg_mask, num, j + 0, 16);
                float c1 = __shfl_sync(seg_mask, num, j + 1, 16);
                float c2 = __shfl_sync(seg_mask, num, j + 2, 16);
                float c3 = __shfl_sync(seg_mask, num, j + 3, 16);
                int  s0 = __shfl_sync(seg_mask, s, j + 0, 16);
                int  s1 = __shfl_sync(seg_mask, s, j + 1, 16);
                int  s2 = __shfl_sync(seg_mask, s, j + 2, 16);
                int  s3 = __shfl_sync(seg_mask, s, j + 3, 16);
                float4 h0 = __ldg((const float4*)(g_h + (size_t)s0 * 64) + ln);
                float4 h1 = __ldg((const float4*)(g_h + (size_t)s1 * 64) + ln);
                float4 h2 = __ldg((const float4*)(g_h + (size_t)s2 * 64) + ln);
                float4 h3 = __ldg((const float4*)(g_h + (size_t)s3 * 64) + ln);
                fma2(acc01, pk2(h0.x, h0.y), pk2(c0, c0));
                fma2(acc23, pk2(h0.z, h0.w), pk2(c0, c0));
                fma2(acc01, pk2(h1.x, h1.y), pk2(c1, c1));
                fma2(acc23, pk2(h1.z, h1.w), pk2(c1, c1));
                fma2(acc01, pk2(h2.x, h2.y), pk2(c2, c2));
                fma2(acc23, pk2(h2.z, h2.w), pk2(c2, c2));
                fma2(acc01, pk2(h3.x, h3.y), pk2(c3, c3));
                fma2(acc23, pk2(h3.z, h3.w), pk2(c3, c3));
            }
            for (; j < cnt; j++) {
                float c = __shfl_sync(seg_mask, num, j, 16);
                int  ss = __shfl_sync(seg_mask, s, j, 16);
                float4 hv = __ldg((const float4*)(g_h + (size_t)ss * 64) + ln);
                unsigned long long cc = pk2(c, c);
                fma2(acc01, pk2(hv.x, hv.y), cc);
                fma2(acc23, pk2(hv.z, hv.w), cc);
            }
        }
    }
#pragma unroll
    for (int o = 8; o; o >>= 1) den += __shfl_xor_sync(seg_mask, den, o, 16);

    float inv = 1.f / (den + 1e-16f);
    float4 a, b4 = ((const float4*)b)[ln];
    unpk2(acc01, a.x, a.y);
    unpk2(acc23, a.z, a.w);
    float4 o4;
    o4.x = fmaxf(a.x * inv + b4.x, 0.f);
    o4.y = fmaxf(a.y * inv + b4.y, 0.f);
    o4.z = fmaxf(a.z * inv + b4.z, 0.f);
    o4.w = fmaxf(a.w * inv + b4.w, 0.f);
    *((float4*)(g_act + (size_t)node * 64) + ln) = o4;
}

// ================= pooling (with fused root detection) / head =================
__global__ void k_pool(const int* __restrict__ batch) {
    int n0 = blockIdx.x * 128;
    int c = threadIdx.x;          // 0..63
    int nend = min(n0 + 128, NN);
    float cur = 0.f; int curg = -1;
    for (int n = n0 + threadIdx.y; n < nend; n += 4) {
        int g = batch[n];
        if (c == 0) {             // root detection: first index of each graph
            if (n == 0 || batch[n - 1] != g) atomicMin(&g_root[g], n);
        }
        float v = g_act[(size_t)n * 64 + c];
        if (g != curg) {
            if (curg >= 0) atomicMaxF(&g_pool[curg * 64 + c], cur);
            curg = g; cur = v;
        } else {
            cur = fmaxf(cur, v);
        }
    }
    if (curg >= 0) atomicMaxF(&g_pool[curg * 64 + c], cur);
}

__global__ void k_head(const float* __restrict__ x,
                       const float* __restrict__ lnW, const float* __restrict__ lnb,
                       const float* __restrict__ l0W, const float* __restrict__ l0b,
                       const float* __restrict__ l1W, const float* __restrict__ l1b,
                       float* __restrict__ out) {
    int g = blockIdx.x;
    int c = threadIdx.x;   // 0..63
    __shared__ float red[2];

    float acc = l0b[c];
#pragma unroll 8
    for (int k = 0; k < 64; k++) acc += g_pool[g * 64 + k] * l0W[k * 64 + c];
    float hp = fmaxf(acc, 0.f);

    const float* xr = x + (size_t)g_root[g] * DIN0;
    float accn = lnb[c];
#pragma unroll 8
    for (int k = 0; k < 128; k++) accn += xr[k] * lnW[k * 64 + c];
    float nw = fmaxf(accn, 0.f);

    float p = hp * l1W[c] + nw * l1W[64 + c];
#pragma unroll
    for (int o = 16; o; o >>= 1) p += __shfl_xor_sync(0xFFFFFFFFu, p, o);
    if ((c & 31) == 0) red[c >> 5] = p;
    __syncthreads();
    if (c == 0) {
        float z = red[0] + red[1] + l1b[0];
        out[g] = 1.f / (1.f + __expf(-z));
    }
}

// ================= launch =================
extern "C" void kernel_launch(void* const* d_in, const int* in_sizes, int n_in,
                              void* d_out, int out_size) {
    const float* x      = (const float*)d_in[0];
    const int*   adj    = (const int*)d_in[1];
    const int*   batch  = (const int*)d_in[2];
    const float* W1     = (const float*)d_in[3];
    const float* asrc1  = (const float*)d_in[4];
    const float* adst1  = (const float*)d_in[5];
    const float* b1     = (const float*)d_in[6];
    const float* W2     = (const float*)d_in[7];
    const float* asrc2  = (const float*)d_in[8];
    const float* adst2  = (const float*)d_in[9];
    const float* b2     = (const float*)d_in[10];
    const float* W3     = (const float*)d_in[11];
    const float* asrc3  = (const float*)d_in[12];
    const float* adst3  = (const float*)d_in[13];
    const float* b3     = (const float*)d_in[14];
    const float* lnW    = (const float*)d_in[15];
    const float* lnb    = (const float*)d_in[16];
    const float* l0W    = (const float*)d_in[17];
    const float* l0b    = (const float*)d_in[18];
    const float* l1W    = (const float*)d_in[19];
    const float* l1b    = (const float*)d_in[20];
    float* out = (float*)d_out;

    const int* src = adj;
    const int* dst = adj + EE;

    void* p_deg = nullptr;
    cudaGetSymbolAddress(&p_deg, g_deg);

    const int GEMM_GRID  = (NN + 127) / 128;          // 782
    const int EDGE_GRID  = (ET + 255) / 256;          // 4297
    const int AGG_GRID   = (NN * 16 + 255) / 256;     // 6250 (16 lanes per node)

    // ---- CSR build ----
    cudaMemsetAsync(p_deg, 0, NN * sizeof(int));
    k_hist<<<EDGE_GRID, 256>>>(dst);                          // 1
    k_scan_block<<<NBLK, 256>>>();                            // 2 (also inits pool/root)
    k_scan_add<<<NBLK, 256>>>();                              // 3
    k_gemm<128><<<GEMM_GRID, 256>>>(x, W1, asrc1, adst1);     // 4 <- profiled
    k_scatter<<<EDGE_GRID, 256>>>(src, dst);                  // 5
    k_gat_agg<<<AGG_GRID, 256>>>(b1);                         // 6

    // ---- layer 2 / 3 ----
    k_gemm<64><<<GEMM_GRID, 256>>>(nullptr, W2, asrc2, adst2);
    k_gat_agg<<<AGG_GRID, 256>>>(b2);
    k_gemm<64><<<GEMM_GRID, 256>>>(nullptr, W3, asrc3, adst3);
    k_gat_agg<<<AGG_GRID, 256>>>(b3);

    // ---- head ----
    k_pool<<<(NN + 127) / 128, dim3(64, 4)>>>(batch);
    k_head<<<GG, 64>>>(x, lnW, lnb, l0W, l0b, l1W, l1b, out);
}

// round 15
// speedup vs baseline: 1.8949x; 1.0690x over previous
#include <cuda_runtime.h>
#include <cuda_bf16.h>
#include <math_constants.h>

// Problem constants
#define NN 100000
#define EE 1000000
#define ET (NN + EE)        // edges incl. self-loops = 1,100,000
#define GG 64
#define HH 64
#define DIN0 128
#define NBLK ((NN + 255) / 256)   // 391

// ---------------- device scratch (no allocations allowed) ----------------
__device__ float g_h[(size_t)NN * HH];      // h = x @ W (pre-bias)
__device__ float g_act[(size_t)NN * HH];    // relu(agg + b) -> next layer input
__device__ float g_as[NN];                  // h . a_src per node
__device__ float g_ad[NN];                  // h . a_dst per node
__device__ float g_pool[GG * HH];
__device__ int   g_root[GG];

// CSR by dst (rebuilt every call; graph static across layers)
__device__ int g_deg[NN];
__device__ int g_tmp[NN];          // block-local exclusive scan
__device__ int g_part[NBLK];       // per-block sums
__device__ int g_row[NN + 1];
__device__ int g_cursor[NN];
__device__ int g_csr_src[ET];

// ---------------- helpers ----------------
__device__ __forceinline__ void atomicMaxF(float* addr, float v) {
    if (v >= 0.f) atomicMax((int*)addr, __float_as_int(v));
    else          atomicMin((unsigned int*)addr, __float_as_uint(v));
}

__device__ __forceinline__ unsigned long long pk2(float lo, float hi) {
    unsigned long long r;
    asm("mov.b64 %0, {%1,%2};" : "=l"(r) : "f"(lo), "f"(hi));
    return r;
}
__device__ __forceinline__ void unpk2(unsigned long long v, float& lo, float& hi) {
    asm("mov.b64 {%0,%1}, %2;" : "=f"(lo), "=f"(hi) : "l"(v));
}
__device__ __forceinline__ void fma2(unsigned long long& acc, unsigned long long a,
                                     unsigned long long b) {
    asm("fma.rn.f32x2 %0, %1, %2, %0;" : "+l"(acc) : "l"(a), "l"(b));
}

// ================= CSR build =================
__global__ void k_hist(const int* __restrict__ dst) {
    int e = blockIdx.x * blockDim.x + threadIdx.x;
    if (e >= ET) return;
    int d = (e < EE) ? dst[e] : (e - EE);
    atomicAdd(&g_deg[d], 1);
}

__global__ void k_scan_block() {
    __shared__ int sm[256];
    int t = threadIdx.x;
    int i = blockIdx.x * 256 + t;
    // fold head-state init in here
    if (i < GG * HH) g_pool[i] = -CUDART_INF_F;
    if (i < GG) g_root[i] = 0x7FFFFFFF;
    int v = (i < NN) ? g_deg[i] : 0;
    sm[t] = v;
    __syncthreads();
#pragma unroll
    for (int off = 1; off < 256; off <<= 1) {
        int u = (t >= off) ? sm[t - off] : 0;
        __syncthreads();
        sm[t] += u;
        __syncthreads();
    }
    if (i < NN) g_tmp[i] = sm[t] - v;       // exclusive within block
    if (t == 255) g_part[blockIdx.x] = sm[255];
}

// fused: per-block prefix of g_part + final add
__global__ void k_scan_add() {
    __shared__ int s_sum;
    int t = threadIdx.x, bid = blockIdx.x;
    if (t == 0) s_sum = 0;
    __syncthreads();
    int v = 0;
    for (int j = t; j < bid; j += 256) v += g_part[j];
#pragma unroll
    for (int o = 16; o; o >>= 1) v += __shfl_xor_sync(0xFFFFFFFFu, v, o);
    if ((t & 31) == 0 && v) atomicAdd(&s_sum, v);
    __syncthreads();
    int i = bid * 256 + t;
    if (i < NN) {
        int r = g_tmp[i] + s_sum;
        g_row[i] = r;
        g_cursor[i] = r;
    }
    if (i == 0) g_row[NN] = ET;
}

__global__ void k_scatter(const int* __restrict__ src, const int* __restrict__ dst) {
    int e = blockIdx.x * blockDim.x + threadIdx.x;
    if (e >= ET) return;
    int s, d;
    if (e < EE) { s = src[e]; d = dst[e]; } else { s = d = e - EE; }
    int pos = atomicAdd(&g_cursor[d], 1);
    g_csr_src[pos] = s;
}

// ================= GEMM + fused alpha epilogue =================
// (unchanged — 128x64 tile, 4x8 micro-tile, 3 CTAs/SM, double-buffered)
template <int DIN>
__global__ void __launch_bounds__(256, 3) k_gemm(
        const float* __restrict__ A, const float* __restrict__ W,
        const float* __restrict__ asrc, const float* __restrict__ adst) {
    __shared__ float As[2][16][256];    // [buf][k][padded slot]: 32 groups * 8
    __shared__ float Bs[2][16][64];

    const float* Ap = A ? A : g_act;
    int tid = threadIdx.x;
    int rg = tid >> 3;               // 0..31 row group (4 rows each)
    int cg = tid & 7;                // 0..7 col group
    int row0 = blockIdx.x * 128;

    int lrow = tid >> 1;
    int lk   = (tid & 1) * 8;
    int slot = (lrow >> 2) * 8 + (lrow & 3);
    int bk = tid >> 4, bq = tid & 15;

    unsigned long long acc[4][4] = {};  // 4 rows x 8 cols (4 f32x2)

    int arow = row0 + lrow;
    const float* aptr = (arow < NN) ? (Ap + (size_t)arow * DIN + lk) : nullptr;
    const float* bptr = W + (size_t)bk * 64 + bq * 4;

    constexpr int NIT = DIN / 16;
    float4 pa0, pa1, pb;

    pa0 = make_float4(0.f, 0.f, 0.f, 0.f);
    pa1 = pa0;
    if (aptr) { pa0 = *(const float4*)(aptr); pa1 = *(const float4*)(aptr + 4); }
    pb = *(const float4*)(bptr);
    {
        As[0][lk + 0][slot] = pa0.x;  As[0][lk + 1][slot] = pa0.y;
        As[0][lk + 2][slot] = pa0.z;  As[0][lk + 3][slot] = pa0.w;
        As[0][lk + 4][slot] = pa1.x;  As[0][lk + 5][slot] = pa1.y;
        As[0][lk + 6][slot] = pa1.z;  As[0][lk + 7][slot] = pa1.w;
        *(float4*)(&Bs[0][bk][bq * 4]) = pb;
    }
    __syncthreads();

    for (int it = 0; it < NIT; ++it) {
        int cur = it & 1;
        if (it + 1 < NIT) {
            int k0 = (it + 1) * 16;
            pa0 = make_float4(0.f, 0.f, 0.f, 0.f);
            pa1 = pa0;
            if (aptr) { pa0 = *(const float4*)(aptr + k0); pa1 = *(const float4*)(aptr + k0 + 4); }
            pb = *(const float4*)(bptr + (size_t)k0 * 64);
        }

#pragma unroll
        for (int k = 0; k < 16; k++) {
            float4 av  = *(float4*)(&As[cur][k][rg * 8]);
            float4 blo = *(float4*)(&Bs[cur][k][cg * 4]);
            float4 bhi = *(float4*)(&Bs[cur][k][32 + cg * 4]);
            unsigned long long b0 = pk2(blo.x, blo.y);
            unsigned long long b1 = pk2(blo.z, blo.w);
            unsigned long long b2 = pk2(bhi.x, bhi.y);
            unsigned long long b3 = pk2(bhi.z, bhi.w);
            float a[4] = {av.x, av.y, av.z, av.w};
#pragma unroll
            for (int r = 0; r < 4; r++) {
                unsigned long long ad = pk2(a[r], a[r]);
                fma2(acc[r][0], ad, b0);
                fma2(acc[r][1], ad, b1);
                fma2(acc[r][2], ad, b2);
                fma2(acc[r][3], ad, b3);
            }
        }

        if (it + 1 < NIT) {
            int nxt = cur ^ 1;
            As[nxt][lk + 0][slot] = pa0.x;  As[nxt][lk + 1][slot] = pa0.y;
            As[nxt][lk + 2][slot] = pa0.z;  As[nxt][lk + 3][slot] = pa0.w;
            As[nxt][lk + 4][slot] = pa1.x;  As[nxt][lk + 5][slot] = pa1.y;
            As[nxt][lk + 6][slot] = pa1.z;  As[nxt][lk + 7][slot] = pa1.w;
            *(float4*)(&Bs[nxt][bk][bq * 4]) = pb;
        }
        __syncthreads();
    }

    float4 aslo = *(const float4*)(asrc + cg * 4);
    float4 ashi = *(const float4*)(asrc + 32 + cg * 4);
    float4 adlo = *(const float4*)(adst + cg * 4);
    float4 adhi = *(const float4*)(adst + 32 + cg * 4);
    int lane = tid & 31;
    unsigned seg_mask = 0xFFu << (lane & 24);

#pragma unroll
    for (int i = 0; i < 4; i++) {
        int r = row0 + rg * 4 + i;
        float4 vlo, vhi;
        unpk2(acc[i][0], vlo.x, vlo.y);
        unpk2(acc[i][1], vlo.z, vlo.w);
        unpk2(acc[i][2], vhi.x, vhi.y);
        unpk2(acc[i][3], vhi.z, vhi.w);
        if (r < NN) {
            float* hp = g_h + (size_t)r * 64;
            *(float4*)(hp + cg * 4)      = vlo;
            *(float4*)(hp + 32 + cg * 4) = vhi;
        }
        float s = vlo.x * aslo.x + vlo.y * aslo.y + vlo.z * aslo.z + vlo.w * aslo.w
                + vhi.x * ashi.x + vhi.y * ashi.y + vhi.z * ashi.z + vhi.w * ashi.w;
        float d = vlo.x * adlo.x + vlo.y * adlo.y + vlo.z * adlo.z + vlo.w * adlo.w
                + vhi.x * adhi.x + vhi.y * adhi.y + vhi.z * adhi.z + vhi.w * adhi.w;
#pragma unroll
        for (int o = 4; o; o >>= 1) {
            s += __shfl_xor_sync(seg_mask, s, o, 8);
            d += __shfl_xor_sync(seg_mask, d, o, 8);
        }
        if (cg == 0 && r < NN) { g_as[r] = s; g_ad[r] = d; }
    }
}

// ================= fused GAT aggregation: 16 lanes per dst node =================
// (unchanged from R14: x4-unrolled gathers, __ldg path)
__global__ void k_gat_agg(const float* __restrict__ b) {
    int t = blockIdx.x * blockDim.x + threadIdx.x;
    int node = t >> 4;
    int ln = threadIdx.x & 15;
    if (node >= NN) return;
    unsigned seg_mask = 0xFFFFu << (threadIdx.x & 16);

    int row = g_row[node], end = g_row[node + 1];
    int deg = end - row;
    float ad = g_ad[node];

    float m = -CUDART_INF_F;
    float myv = 0.f; int mys = 0;
    for (int i = row + ln; i < end; i += 16) {
        int s = __ldg(&g_csr_src[i]);
        float v = __ldg(&g_as[s]) + ad;
        v = fmaxf(v, 0.2f * v);          // leaky_relu(0.2)
        mys = s; myv = v;
        m = fmaxf(m, v);
    }
#pragma unroll
    for (int o = 8; o; o >>= 1) m = fmaxf(m, __shfl_xor_sync(seg_mask, m, o, 16));

    float den = 0.f;
    unsigned long long acc01 = 0, acc23 = 0;

    if (deg <= 16) {
        float num = 0.f; int s = 0;
        if (ln < deg) { num = __expf(myv - m); s = mys; }
        den = num;
        int j = 0;
        for (; j + 4 <= deg; j += 4) {
            float c0 = __shfl_sync(seg_mask, num, j + 0, 16);
            float c1 = __shfl_sync(seg_mask, num, j + 1, 16);
            float c2 = __shfl_sync(seg_mask, num, j + 2, 16);
            float c3 = __shfl_sync(seg_mask, num, j + 3, 16);
            int  s0 = __shfl_sync(seg_mask, s, j + 0, 16);
            int  s1 = __shfl_sync(seg_mask, s, j + 1, 16);
            int  s2 = __shfl_sync(seg_mask, s, j + 2, 16);
            int  s3 = __shfl_sync(seg_mask, s, j + 3, 16);
            float4 h0 = __ldg((const float4*)(g_h + (size_t)s0 * 64) + ln);
            float4 h1 = __ldg((const float4*)(g_h + (size_t)s1 * 64) + ln);
            float4 h2 = __ldg((const float4*)(g_h + (size_t)s2 * 64) + ln);
            float4 h3 = __ldg((const float4*)(g_h + (size_t)s3 * 64) + ln);
            fma2(acc01, pk2(h0.x, h0.y), pk2(c0, c0));
            fma2(acc23, pk2(h0.z, h0.w), pk2(c0, c0));
            fma2(acc01, pk2(h1.x, h1.y), pk2(c1, c1));
            fma2(acc23, pk2(h1.z, h1.w), pk2(c1, c1));
            fma2(acc01, pk2(h2.x, h2.y), pk2(c2, c2));
            fma2(acc23, pk2(h2.z, h2.w), pk2(c2, c2));
            fma2(acc01, pk2(h3.x, h3.y), pk2(c3, c3));
            fma2(acc23, pk2(h3.z, h3.w), pk2(c3, c3));
        }
        for (; j < deg; j++) {
            float c = __shfl_sync(seg_mask, num, j, 16);
            int  ss = __shfl_sync(seg_mask, s, j, 16);
            float4 hv = __ldg((const float4*)(g_h + (size_t)ss * 64) + ln);
            unsigned long long cc = pk2(c, c);
            fma2(acc01, pk2(hv.x, hv.y), cc);
            fma2(acc23, pk2(hv.z, hv.w), cc);
        }
    } else {
        for (int base = row; base < end; base += 16) {
            int i = base + ln;
            int s = 0; float num = 0.f;
            if (i < end) {
                s = __ldg(&g_csr_src[i]);
                float v = __ldg(&g_as[s]) + ad;
                v = fmaxf(v, 0.2f * v);
                num = __expf(v - m);
            }
            den += num;
            int cnt = min(16, end - base);
            int j = 0;
            for (; j + 4 <= cnt; j += 4) {
                float c0 = __shfl_sync(seg_mask, num, j + 0, 16);
                float c1 = __shfl_sync(seg_mask, num, j + 1, 16);
                float c2 = __shfl_sync(seg_mask, num, j + 2, 16);
                float c3 = __shfl_sync(seg_mask, num, j + 3, 16);
                int  s0 = __shfl_sync(seg_mask, s, j + 0, 16);
                int  s1 = __shfl_sync(seg_mask, s, j + 1, 16);
                int  s2 = __shfl_sync(seg_mask, s, j + 2, 16);
                int  s3 = __shfl_sync(seg_mask, s, j + 3, 16);
                float4 h0 = __ldg((const float4*)(g_h + (size_t)s0 * 64) + ln);
                float4 h1 = __ldg((const float4*)(g_h + (size_t)s1 * 64) + ln);
                float4 h2 = __ldg((const float4*)(g_h + (size_t)s2 * 64) + ln);
                float4 h3 = __ldg((const float4*)(g_h + (size_t)s3 * 64) + ln);
                fma2(acc01, pk2(h0.x, h0.y), pk2(c0, c0));
                fma2(acc23, pk2(h0.z, h0.w), pk2(c0, c0));
                fma2(acc01, pk2(h1.x, h1.y), pk2(c1, c1));
                fma2(acc23, pk2(h1.z, h1.w), pk2(c1, c1));
                fma2(acc01, pk2(h2.x, h2.y), pk2(c2, c2));
                fma2(acc23, pk2(h2.z, h2.w), pk2(c2, c2));
                fma2(acc01, pk2(h3.x, h3.y), pk2(c3, c3));
                fma2(acc23, pk2(h3.z, h3.w), pk2(c3, c3));
            }
            for (; j < cnt; j++) {
                float c = __shfl_sync(seg_mask, num, j, 16);
                int  ss = __shfl_sync(seg_mask, s, j, 16);
                float4 hv = __ldg((const float4*)(g_h + (size_t)ss * 64) + ln);
                unsigned long long cc = pk2(c, c);
                fma2(acc01, pk2(hv.x, hv.y), cc);
                fma2(acc23, pk2(hv.z, hv.w), cc);
            }
        }
    }
#pragma unroll
    for (int o = 8; o; o >>= 1) den += __shfl_xor_sync(seg_mask, den, o, 16);

    float inv = 1.f / (den + 1e-16f);
    float4 a, b4 = ((const float4*)b)[ln];
    unpk2(acc01, a.x, a.y);
    unpk2(acc23, a.z, a.w);
    float4 o4;
    o4.x = fmaxf(a.x * inv + b4.x, 0.f);
    o4.y = fmaxf(a.y * inv + b4.y, 0.f);
    o4.z = fmaxf(a.z * inv + b4.z, 0.f);
    o4.w = fmaxf(a.w * inv + b4.w, 0.f);
    *((float4*)(g_act + (size_t)node * 64) + ln) = o4;
}

// ================= pooling (with fused root detection) / head =================
__global__ void k_pool(const int* __restrict__ batch) {
    int n0 = blockIdx.x * 128;
    int c = threadIdx.x;          // 0..63
    int nend = min(n0 + 128, NN);
    float cur = 0.f; int curg = -1;
    for (int n = n0 + threadIdx.y; n < nend; n += 4) {
        int g = batch[n];
        if (c == 0) {             // root detection: first index of each graph
            if (n == 0 || batch[n - 1] != g) atomicMin(&g_root[g], n);
        }
        float v = g_act[(size_t)n * 64 + c];
        if (g != curg) {
            if (curg >= 0) atomicMaxF(&g_pool[curg * 64 + c], cur);
            curg = g; cur = v;
        } else {
            cur = fmaxf(cur, v);
        }
    }
    if (curg >= 0) atomicMaxF(&g_pool[curg * 64 + c], cur);
}

__global__ void k_head(const float* __restrict__ x,
                       const float* __restrict__ lnW, const float* __restrict__ lnb,
                       const float* __restrict__ l0W, const float* __restrict__ l0b,
                       const float* __restrict__ l1W, const float* __restrict__ l1b,
                       float* __restrict__ out) {
    int g = blockIdx.x;
    int c = threadIdx.x;   // 0..63
    __shared__ float red[2];

    float acc = l0b[c];
#pragma unroll 8
    for (int k = 0; k < 64; k++) acc += g_pool[g * 64 + k] * l0W[k * 64 + c];
    float hp = fmaxf(acc, 0.f);

    const float* xr = x + (size_t)g_root[g] * DIN0;
    float accn = lnb[c];
#pragma unroll 8
    for (int k = 0; k < 128; k++) accn += xr[k] * lnW[k * 64 + c];
    float nw = fmaxf(accn, 0.f);

    float p = hp * l1W[c] + nw * l1W[64 + c];
#pragma unroll
    for (int o = 16; o; o >>= 1) p += __shfl_xor_sync(0xFFFFFFFFu, p, o);
    if ((c & 31) == 0) red[c >> 5] = p;
    __syncthreads();
    if (c == 0) {
        float z = red[0] + red[1] + l1b[0];
        out[g] = 1.f / (1.f + __expf(-z));
    }
}

// ================= launch =================
extern "C" void kernel_launch(void* const* d_in, const int* in_sizes, int n_in,
                              void* d_out, int out_size) {
    const float* x      = (const float*)d_in[0];
    const int*   adj    = (const int*)d_in[1];
    const int*   batch  = (const int*)d_in[2];
    const float* W1     = (const float*)d_in[3];
    const float* asrc1  = (const float*)d_in[4];
    const float* adst1  = (const float*)d_in[5];
    const float* b1     = (const float*)d_in[6];
    const float* W2     = (const float*)d_in[7];
    const float* asrc2  = (const float*)d_in[8];
    const float* adst2  = (const float*)d_in[9];
    const float* b2     = (const float*)d_in[10];
    const float* W3     = (const float*)d_in[11];
    const float* asrc3  = (const float*)d_in[12];
    const float* adst3  = (const float*)d_in[13];
    const float* b3     = (const float*)d_in[14];
    const float* lnW    = (const float*)d_in[15];
    const float* lnb    = (const float*)d_in[16];
    const float* l0W    = (const float*)d_in[17];
    const float* l0b    = (const float*)d_in[18];
    const float* l1W    = (const float*)d_in[19];
    const float* l1b    = (const float*)d_in[20];
    float* out = (float*)d_out;

    const int* src = adj;
    const int* dst = adj + EE;

    void* p_deg = nullptr;
    cudaGetSymbolAddress(&p_deg, g_deg);

    const int GEMM_GRID  = (NN + 127) / 128;          // 782
    const int EDGE_GRID  = (ET + 255) / 256;          // 4297
    const int AGG_GRID   = (NN * 16 + 255) / 256;     // 6250 (16 lanes per node)

    // ---- fork: CSR build (stream s2) runs concurrently with gemm1 (main) ----
    cudaStream_t s2;
    cudaStreamCreateWithFlags(&s2, cudaStreamNonBlocking);
    cudaEvent_t evF, evJ;
    cudaEventCreateWithFlags(&evF, cudaEventDisableTiming);
    cudaEventCreateWithFlags(&evJ, cudaEventDisableTiming);

    cudaEventRecord(evF, 0);                 // fork point on capture stream
    cudaStreamWaitEvent(s2, evF, 0);

    // branch B (s2): CSR build — independent of gemm1
    cudaMemsetAsync(p_deg, 0, NN * sizeof(int), s2);
    k_hist<<<EDGE_GRID, 256, 0, s2>>>(dst);
    k_scan_block<<<NBLK, 256, 0, s2>>>();            // also inits pool/root
    k_scan_add<<<NBLK, 256, 0, s2>>>();
    k_scatter<<<EDGE_GRID, 256, 0, s2>>>(src, dst);
    cudaEventRecord(evJ, s2);

    // branch A (main stream): gemm1 — needs only x, W1
    k_gemm<128><<<GEMM_GRID, 256>>>(x, W1, asrc1, adst1);

    cudaStreamWaitEvent(0, evJ, 0);          // join before agg1

    // ---- layer 1 aggregation, then layers 2/3 (serial chain) ----
    k_gat_agg<<<AGG_GRID, 256>>>(b1);
    k_gemm<64><<<GEMM_GRID, 256>>>(nullptr, W2, asrc2, adst2);
    k_gat_agg<<<AGG_GRID, 256>>>(b2);
    k_gemm<64><<<GEMM_GRID, 256>>>(nullptr, W3, asrc3, adst3);
    k_gat_agg<<<AGG_GRID, 256>>>(b3);

    // ---- head ----
    k_pool<<<(NN + 127) / 128, dim3(64, 4)>>>(batch);
    k_head<<<GG, 64>>>(x, lnW, lnb, l0W, l0b, l1W, l1b, out);

    cudaEventDestroy(evF);
    cudaEventDestroy(evJ);
    cudaStreamDestroy(s2);
}